// round 11
// baseline (speedup 1.0000x reference)
#include <cuda_runtime.h>
#include <cstdint>
#include <cstddef>

#define BB 8
#define NN 2048
#define HE 4
#define HD 32
#define SPLIT 4
#define NCH ((NN / SPLIT) / 32)      // 16 chunks of 32 j per CTA

typedef unsigned long long ull;

// ---------------- device scratch ----------------
__device__ float    g_Wh[BB * NN * 128];            // 8 MB
__device__ float2   g_ip2[BB * NN * HE];            // 512KB {e^s, e^{0.2s}}
__device__ float2   g_jp2[BB * NN * HE];            // 512KB {e^t, e^{0.2t}}
__device__ unsigned g_Ab[BB * NN * (NN / 32)];      // 4 MB  packed adjacency
__device__ float    g_pacc[SPLIT * BB * NN * 128];  // 33.5MB unnormalized partials
__device__ float    g_pz[SPLIT * BB * NN * HE];     // 1 MB  partial row sums

// ---------------- helpers ----------------
__device__ __forceinline__ ull packf2(float lo, float hi) {
    ull r; asm("mov.b64 %0,{%1,%2};" : "=l"(r) : "f"(lo), "f"(hi)); return r;
}
__device__ __forceinline__ void unpackf2(ull v, float& lo, float& hi) {
    asm("mov.b64 {%0,%1},%2;" : "=f"(lo), "=f"(hi) : "l"(v));
}
__device__ __forceinline__ void cpa16(void* dst, const void* src) {
    unsigned d = (unsigned)__cvta_generic_to_shared(dst);
    asm volatile("cp.async.cg.shared.global [%0], [%1], 16;" :: "r"(d), "l"(src));
}
__device__ __forceinline__ void cpa8(void* dst, const void* src) {
    unsigned d = (unsigned)__cvta_generic_to_shared(dst);
    asm volatile("cp.async.ca.shared.global [%0], [%1], 8;" :: "r"(d), "l"(src));
}
__device__ __forceinline__ void cpcommit() { asm volatile("cp.async.commit_group;"); }
__device__ __forceinline__ void cpwait1()  { asm volatile("cp.async.wait_group 1;"); }

// ---------------- K1: Wh = h @ W ----------------
__global__ __launch_bounds__(256) void k_mm(const float* __restrict__ hmat,
                                            const float* __restrict__ W) {
    __shared__ float hs[64 * 36];
    __shared__ float Ws[32 * 128];
    int tid = threadIdx.x;
    int tx = tid & 15, ty = tid >> 4;
    int rbase = blockIdx.x * 64;

    float acc[4][8];
#pragma unroll
    for (int i = 0; i < 4; ++i)
#pragma unroll
        for (int j = 0; j < 8; ++j) acc[i][j] = 0.f;

    for (int k0 = 0; k0 < 128; k0 += 32) {
        __syncthreads();
#pragma unroll
        for (int m = 0; m < 2; ++m) {
            int idx = tid * 2 + m;
            int r = idx >> 3, q = idx & 7;
            *(float4*)(hs + r * 36 + q * 4) =
                *(const float4*)(hmat + (size_t)(rbase + r) * 128 + k0 + q * 4);
        }
#pragma unroll
        for (int m = 0; m < 4; ++m) {
            int idx = tid + 256 * m;
            int kk = idx >> 5, c4 = idx & 31;
            *(float4*)(Ws + kk * 128 + c4 * 4) =
                *(const float4*)(W + (size_t)(k0 + kk) * 128 + c4 * 4);
        }
        __syncthreads();
#pragma unroll
        for (int kk = 0; kk < 32; ++kk) {
            float av[4], bv[8];
#pragma unroll
            for (int i = 0; i < 4; ++i) av[i] = hs[(ty * 4 + i) * 36 + kk];
#pragma unroll
            for (int j = 0; j < 8; ++j) bv[j] = Ws[kk * 128 + tx + 16 * j];
#pragma unroll
            for (int i = 0; i < 4; ++i)
#pragma unroll
                for (int j = 0; j < 8; ++j) acc[i][j] += av[i] * bv[j];
        }
    }
#pragma unroll
    for (int i = 0; i < 4; ++i)
#pragma unroll
        for (int j = 0; j < 8; ++j)
            g_Wh[(size_t)(rbase + ty * 4 + i) * 128 + tx + 16 * j] = acc[i][j];
}

// ---------------- K2: per-(node,head) params ----------------
__global__ __launch_bounds__(256) void k_params(const float* __restrict__ a) {
    __shared__ float sa[64];
    int tid = threadIdx.x;
    if (tid < 64) sa[tid] = a[tid];
    __syncthreads();
    int idx = blockIdx.x * 256 + tid;
    int nh = idx >> 2, hh = idx & 3;
    const float4* wh = (const float4*)(g_Wh + (size_t)nh * 128 + hh * 32);
    float s = 0.f, t = 0.f;
#pragma unroll
    for (int k = 0; k < 8; ++k) {
        float4 w = wh[k];
        s += w.x * sa[4 * k + 0] + w.y * sa[4 * k + 1] + w.z * sa[4 * k + 2] + w.w * sa[4 * k + 3];
        t += w.x * sa[32 + 4 * k + 0] + w.y * sa[32 + 4 * k + 1] + w.z * sa[32 + 4 * k + 2] + w.w * sa[32 + 4 * k + 3];
    }
    g_ip2[idx] = make_float2(expf(s), expf(0.2f * s));
    g_jp2[idx] = make_float2(expf(t), expf(0.2f * t));
}

// ---------------- K3: pack A into bitmasks ----------------
__global__ __launch_bounds__(256) void k_pack(const int* __restrict__ A) {
    int gt = blockIdx.x * 256 + threadIdx.x;
    int warpId = gt >> 5, lane = gt & 31;
    const int* src = A + (size_t)warpId * 1024;
    unsigned keep = 0;
#pragma unroll
    for (int g = 0; g < 32; ++g) {
        int v = src[g * 32 + lane];
        unsigned m = __ballot_sync(0xffffffffu, v > 0);
        if (g == lane) keep = m;
    }
    g_Ab[(size_t)warpId * 32 + lane] = keep;
}

// ---------------- K4: fused attention, j-split x4, partial output ----------
// CTA = (split, batch, 32-row block); 128 threads; 5 CTAs/SM.
// Consume path identical to round-10 passing kernel; staging via cp.async.
__global__ __launch_bounds__(128, 5) void k_attn() {
    constexpr int JC = 32;
    __shared__ float  sWh[2][JC * 128];     // 16 KB per buffer
    __shared__ float2 sJP[2][JC * HE];      // 1 KB per buffer

    int tid = threadIdx.x;
    int sp = blockIdx.x & 3;                  // j-split id
    int blk = blockIdx.x >> 2;
    int b = blk >> 6;
    int ibase = (blk & 63) << 5;
    int il = tid & 15, hh = tid >> 4;
    int h = hh >> 1, half = hh & 1;
    int i0 = ibase + il * 2;
    int dimoff = h * 32 + half * 16;
    size_t bn = (size_t)b * NN;
    int c0 = sp * NCH;                        // first absolute 32-j chunk

    float2 e0 = g_ip2[(bn + i0) * 4 + h];
    float2 e1 = g_ip2[(bn + i0 + 1) * 4 + h];

    const float*    gWh = g_Wh + bn * 128;
    const float2*   gJP = g_jp2 + bn * 4;
    const unsigned* gA0 = g_Ab + (bn + i0) * 64;
    const unsigned* gA1 = gA0 + 64;

    ull acc[2][8];
#pragma unroll
    for (int r = 0; r < 2; ++r)
#pragma unroll
        for (int k = 0; k < 8; ++k) acc[r][k] = 0ull;
    float z0 = 0.f, z1 = 0.f;

    // prologue: stage chunks c0, c0+1 via cp.async (two groups)
#pragma unroll
    for (int s = 0; s < 2; ++s) {
        const float* src = gWh + (size_t)(c0 + s) * JC * 128 + tid * 32;
#pragma unroll
        for (int k = 0; k < 8; ++k)
            cpa16(&sWh[s][tid * 32 + k * 4], src + k * 4);
        cpa8(&sJP[s][tid], gJP + (size_t)(c0 + s) * JC * 4 + tid);
        cpcommit();
    }
    unsigned wa0 = gA0[c0], wa1 = gA1[c0];

    for (int c = 0; c < NCH; ++c) {
        cpwait1();                  // chunk c staged (groups: 2 prologue + 1/iter)
        __syncthreads();
        int cur = c & 1;

        unsigned na0 = 0, na1 = 0;
        if (c + 1 < NCH) { na0 = gA0[c0 + c + 1]; na1 = gA1[c0 + c + 1]; }

        int m0 = (int)__brev(wa0), m1 = (int)__brev(wa1);
        const float*  whc = sWh[cur];
        const float2* jpc = sJP[cur];

#pragma unroll 4
        for (int jj = 0; jj < JC; ++jj) {
            float2 jp = jpc[jj * 4 + h];                 // {u_j, v_j}
            float p0 = fmaxf(e0.x * jp.x, e0.y * jp.y);  // exp(leakyrelu(s+t))
            float p1 = fmaxf(e1.x * jp.x, e1.y * jp.y);
            p0 = (m0 < 0) ? p0 : 0.0f;
            p1 = (m1 < 0) ? p1 : 0.0f;
            m0 <<= 1; m1 <<= 1;
            z0 += p0; z1 += p1;

            ull P0 = packf2(p0, p0);
            ull P1 = packf2(p1, p1);

            const float4* wr = (const float4*)&whc[jj * 128 + dimoff];
#pragma unroll
            for (int k = 0; k < 4; ++k) {
                ulonglong2 w = *reinterpret_cast<const ulonglong2*>(wr + k);
                asm("fma.rn.f32x2 %0, %1, %2, %0;" : "+l"(acc[0][2 * k])     : "l"(w.x), "l"(P0));
                asm("fma.rn.f32x2 %0, %1, %2, %0;" : "+l"(acc[0][2 * k + 1]) : "l"(w.y), "l"(P0));
                asm("fma.rn.f32x2 %0, %1, %2, %0;" : "+l"(acc[1][2 * k])     : "l"(w.x), "l"(P1));
                asm("fma.rn.f32x2 %0, %1, %2, %0;" : "+l"(acc[1][2 * k + 1]) : "l"(w.y), "l"(P1));
            }
        }

        __syncthreads();            // all threads done reading buf[cur]
        if (c + 2 < NCH) {          // refill buf[cur] with chunk c+2
            const float* src = gWh + (size_t)(c0 + c + 2) * JC * 128 + tid * 32;
#pragma unroll
            for (int k = 0; k < 8; ++k)
                cpa16(&sWh[cur][tid * 32 + k * 4], src + k * 4);
            cpa8(&sJP[cur][tid], gJP + (size_t)(c0 + c + 2) * JC * 4 + tid);
        }
        cpcommit();                 // one group per iter (possibly empty)
        wa0 = na0; wa1 = na1;
    }

    // epilogue: store UNNORMALIZED partials + partial z
    size_t sbase = (size_t)sp * BB * NN;
#pragma unroll
    for (int r = 0; r < 2; ++r) {
        float* o = g_pacc + (sbase + bn + i0 + r) * 128 + dimoff;
#pragma unroll
        for (int k = 0; k < 4; ++k) {
            float a0, a1, a2, a3;
            unpackf2(acc[r][2 * k],     a0, a1);
            unpackf2(acc[r][2 * k + 1], a2, a3);
            ((float4*)o)[k] = make_float4(a0, a1, a2, a3);
        }
    }
    if (half == 0) {
        g_pz[(sbase + bn + i0) * HE + h]     = z0;
        g_pz[(sbase + bn + i0 + 1) * HE + h] = z1;
    }
}

// ---------------- K5: combine 4 partials + normalize ----------------
// thread = (row, 4-dim group). 16384 rows * 32 groups = 524288 threads.
__global__ __launch_bounds__(256) void k_reduce(float* __restrict__ out) {
    int idx = blockIdx.x * 256 + threadIdx.x;
    int row = idx >> 5, q = idx & 31;
    int h = q >> 3;

    float z = 0.f;
#pragma unroll
    for (int s = 0; s < SPLIT; ++s)
        z += g_pz[((size_t)s * BB * NN + row) * HE + h];

    float4 acc = make_float4(0.f, 0.f, 0.f, 0.f);
#pragma unroll
    for (int s = 0; s < SPLIT; ++s) {
        float4 v = *(const float4*)&g_pacc[((size_t)s * BB * NN + row) * 128 + q * 4];
        acc.x += v.x; acc.y += v.y; acc.z += v.z; acc.w += v.w;
    }
    float rz = 1.0f / z;
    ((float4*)out)[idx] = make_float4(acc.x * rz, acc.y * rz, acc.z * rz, acc.w * rz);
}

// ---------------- launch ----------------
extern "C" void kernel_launch(void* const* d_in, const int* in_sizes, int n_in,
                              void* d_out, int out_size) {
    const float* h = nullptr;
    const int*   A = nullptr;
    const float* W = nullptr;
    const float* a = nullptr;
    for (int i = 0; i < n_in; ++i) {
        switch (in_sizes[i]) {
            case BB * NN * 128:      h = (const float*)d_in[i]; break;
            case 128 * 128:          W = (const float*)d_in[i]; break;
            case 2 * HD:             a = (const float*)d_in[i]; break;
            default:                 A = (const int*)d_in[i];   break;
        }
    }
    float* out = (float*)d_out;

    k_mm    <<<(BB * NN) / 64, 256>>>(h, W);
    k_params<<<(BB * NN * HE) / 256, 256>>>(a);
    k_pack  <<<4096, 256>>>(A);
    k_attn  <<<BB * (NN / 32) * SPLIT, 128>>>();
    k_reduce<<<(BB * NN * 32) / 256, 256>>>(out);
}

// round 12
// speedup vs baseline: 1.2291x; 1.2291x over previous
#include <cuda_runtime.h>
#include <cstdint>
#include <cstddef>

#define BB 8
#define NN 2048
#define HE 4
#define HD 32
#define SPLIT 4
#define NCH ((NN / SPLIT) / 32)      // 16 chunks of 32 j per CTA

typedef unsigned long long ull;

// ---------------- device scratch ----------------
__device__ float    g_Wh[BB * NN * 128];            // 8 MB
__device__ float2   g_ip2[BB * NN * HE];            // 512KB {e^s, e^{0.2s}}
__device__ float2   g_jp2[BB * NN * HE];            // 512KB {e^t, e^{0.2t}}
__device__ unsigned g_Ab[BB * NN * (NN / 32)];      // 4 MB  packed adjacency
__device__ float    g_pacc[SPLIT * BB * NN * 128];  // 33.5MB unnormalized partials
__device__ float    g_pz[SPLIT * BB * NN * HE];     // 1 MB  partial row sums

// ---------------- helpers ----------------
__device__ __forceinline__ ull packf2(float lo, float hi) {
    ull r; asm("mov.b64 %0,{%1,%2};" : "=l"(r) : "f"(lo), "f"(hi)); return r;
}
__device__ __forceinline__ void unpackf2(ull v, float& lo, float& hi) {
    asm("mov.b64 {%0,%1},%2;" : "=f"(lo), "=f"(hi) : "l"(v));
}

// ---------------- K1: Wh = h @ W ----------------
__global__ __launch_bounds__(256) void k_mm(const float* __restrict__ hmat,
                                            const float* __restrict__ W) {
    __shared__ float hs[64 * 36];
    __shared__ float Ws[32 * 128];
    int tid = threadIdx.x;
    int tx = tid & 15, ty = tid >> 4;
    int rbase = blockIdx.x * 64;

    float acc[4][8];
#pragma unroll
    for (int i = 0; i < 4; ++i)
#pragma unroll
        for (int j = 0; j < 8; ++j) acc[i][j] = 0.f;

    for (int k0 = 0; k0 < 128; k0 += 32) {
        __syncthreads();
#pragma unroll
        for (int m = 0; m < 2; ++m) {
            int idx = tid * 2 + m;
            int r = idx >> 3, q = idx & 7;
            *(float4*)(hs + r * 36 + q * 4) =
                *(const float4*)(hmat + (size_t)(rbase + r) * 128 + k0 + q * 4);
        }
#pragma unroll
        for (int m = 0; m < 4; ++m) {
            int idx = tid + 256 * m;
            int kk = idx >> 5, c4 = idx & 31;
            *(float4*)(Ws + kk * 128 + c4 * 4) =
                *(const float4*)(W + (size_t)(k0 + kk) * 128 + c4 * 4);
        }
        __syncthreads();
#pragma unroll
        for (int kk = 0; kk < 32; ++kk) {
            float av[4], bv[8];
#pragma unroll
            for (int i = 0; i < 4; ++i) av[i] = hs[(ty * 4 + i) * 36 + kk];
#pragma unroll
            for (int j = 0; j < 8; ++j) bv[j] = Ws[kk * 128 + tx + 16 * j];
#pragma unroll
            for (int i = 0; i < 4; ++i)
#pragma unroll
                for (int j = 0; j < 8; ++j) acc[i][j] += av[i] * bv[j];
        }
    }
#pragma unroll
    for (int i = 0; i < 4; ++i)
#pragma unroll
        for (int j = 0; j < 8; ++j)
            g_Wh[(size_t)(rbase + ty * 4 + i) * 128 + tx + 16 * j] = acc[i][j];
}

// ---------------- K2: per-(node,head) params ----------------
__global__ __launch_bounds__(256) void k_params(const float* __restrict__ a) {
    __shared__ float sa[64];
    int tid = threadIdx.x;
    if (tid < 64) sa[tid] = a[tid];
    __syncthreads();
    int idx = blockIdx.x * 256 + tid;
    int nh = idx >> 2, hh = idx & 3;
    const float4* wh = (const float4*)(g_Wh + (size_t)nh * 128 + hh * 32);
    float s = 0.f, t = 0.f;
#pragma unroll
    for (int k = 0; k < 8; ++k) {
        float4 w = wh[k];
        s += w.x * sa[4 * k + 0] + w.y * sa[4 * k + 1] + w.z * sa[4 * k + 2] + w.w * sa[4 * k + 3];
        t += w.x * sa[32 + 4 * k + 0] + w.y * sa[32 + 4 * k + 1] + w.z * sa[32 + 4 * k + 2] + w.w * sa[32 + 4 * k + 3];
    }
    g_ip2[idx] = make_float2(expf(s), expf(0.2f * s));
    g_jp2[idx] = make_float2(expf(t), expf(0.2f * t));
}

// ---------------- K3: pack A into bitmasks ----------------
__global__ __launch_bounds__(256) void k_pack(const int* __restrict__ A) {
    int gt = blockIdx.x * 256 + threadIdx.x;
    int warpId = gt >> 5, lane = gt & 31;
    const int* src = A + (size_t)warpId * 1024;
    unsigned keep = 0;
#pragma unroll
    for (int g = 0; g < 32; ++g) {
        int v = src[g * 32 + lane];
        unsigned m = __ballot_sync(0xffffffffu, v > 0);
        if (g == lane) keep = m;
    }
    g_Ab[(size_t)warpId * 32 + lane] = keep;
}

// ---------------- K4: fused attention, j-split x4, partial output ----------
// CTA = (split, batch, 32-row block); 128 threads; grid 2048.
// Staging: round-10 PROVEN LDG->reg->STS double buffer, ONE barrier per chunk.
// thread = 2 rows x 16 dims; warp Wh LDS has 2 distinct addrs (16-lane bcast).
__global__ __launch_bounds__(128, 4) void k_attn() {
    constexpr int JC = 32;
    __shared__ float  sWh[2][JC * 128];     // 16 KB per buffer
    __shared__ float2 sJP[2][JC * HE];      // 1 KB per buffer

    int tid = threadIdx.x;
    int sp = blockIdx.x & 3;                  // j-split id
    int blk = blockIdx.x >> 2;
    int b = blk >> 6;
    int ibase = (blk & 63) << 5;
    int il = tid & 15, hh = tid >> 4;
    int h = hh >> 1, half = hh & 1;
    int i0 = ibase + il * 2;
    int dimoff = h * 32 + half * 16;
    size_t bn = (size_t)b * NN;
    int c0 = sp * NCH;                        // first absolute 32-j chunk

    float2 e0 = g_ip2[(bn + i0) * 4 + h];
    float2 e1 = g_ip2[(bn + i0 + 1) * 4 + h];

    const float4*   gWh4 = (const float4*)(g_Wh + bn * 128);
    const float2*   gJP  = g_jp2 + bn * 4;
    const unsigned* gA0  = g_Ab + (bn + i0) * 64;
    const unsigned* gA1  = gA0 + 64;

    ull acc[2][8];
#pragma unroll
    for (int r = 0; r < 2; ++r)
#pragma unroll
        for (int k = 0; k < 8; ++k) acc[r][k] = 0ull;
    float z0 = 0.f, z1 = 0.f;

    // prime chunk c0 (32 nodes x 128 dims = 1024 float4; 8 per thread)
#pragma unroll
    for (int m = 0; m < 8; ++m)
        ((float4*)sWh[0])[tid + 128 * m] = gWh4[(size_t)c0 * JC * 32 + tid + 128 * m];
    sJP[0][tid] = gJP[(size_t)c0 * JC * 4 + tid];
    unsigned wa0 = gA0[c0], wa1 = gA1[c0];
    __syncthreads();

    for (int c = 0; c < NCH; ++c) {
        int cur = c & 1, nxt = cur ^ 1;
        float4 r[8]; float2 rj;
        unsigned na0 = 0, na1 = 0;
        bool more = (c + 1 < NCH);
        if (more) {   // prefetch next chunk into registers (hides L2 latency)
            const float4* src = gWh4 + (size_t)(c0 + c + 1) * JC * 32;
#pragma unroll
            for (int m = 0; m < 8; ++m) r[m] = src[tid + 128 * m];
            rj  = gJP[(size_t)(c0 + c + 1) * JC * 4 + tid];
            na0 = gA0[c0 + c + 1];
            na1 = gA1[c0 + c + 1];
        }

        int m0 = (int)__brev(wa0), m1 = (int)__brev(wa1);
        const float*  whc = sWh[cur];
        const float2* jpc = sJP[cur];

#pragma unroll 4
        for (int jj = 0; jj < JC; ++jj) {
            float2 jp = jpc[jj * 4 + h];                 // {u_j, v_j}
            float p0 = fmaxf(e0.x * jp.x, e0.y * jp.y);  // exp(leakyrelu(s+t))
            float p1 = fmaxf(e1.x * jp.x, e1.y * jp.y);
            p0 = (m0 < 0) ? p0 : 0.0f;                   // adjacency bit (MSB-first)
            p1 = (m1 < 0) ? p1 : 0.0f;
            m0 <<= 1; m1 <<= 1;
            z0 += p0; z1 += p1;

            ull P0 = packf2(p0, p0);
            ull P1 = packf2(p1, p1);

            const float4* wr = (const float4*)&whc[jj * 128 + dimoff];
#pragma unroll
            for (int k = 0; k < 4; ++k) {
                ulonglong2 w = *reinterpret_cast<const ulonglong2*>(wr + k);
                asm("fma.rn.f32x2 %0, %1, %2, %0;" : "+l"(acc[0][2 * k])     : "l"(w.x), "l"(P0));
                asm("fma.rn.f32x2 %0, %1, %2, %0;" : "+l"(acc[0][2 * k + 1]) : "l"(w.y), "l"(P0));
                asm("fma.rn.f32x2 %0, %1, %2, %0;" : "+l"(acc[1][2 * k])     : "l"(w.x), "l"(P1));
                asm("fma.rn.f32x2 %0, %1, %2, %0;" : "+l"(acc[1][2 * k + 1]) : "l"(w.y), "l"(P1));
            }
        }

        if (more) {   // write prefetched data into the other buffer
#pragma unroll
            for (int m = 0; m < 8; ++m)
                ((float4*)sWh[nxt])[tid + 128 * m] = r[m];
            sJP[nxt][tid] = rj;
        }
        wa0 = na0; wa1 = na1;
        __syncthreads();
    }

    // epilogue: store UNNORMALIZED partials + partial z
    size_t sbase = (size_t)sp * BB * NN;
#pragma unroll
    for (int r = 0; r < 2; ++r) {
        float* o = g_pacc + (sbase + bn + i0 + r) * 128 + dimoff;
#pragma unroll
        for (int k = 0; k < 4; ++k) {
            float a0, a1, a2, a3;
            unpackf2(acc[r][2 * k],     a0, a1);
            unpackf2(acc[r][2 * k + 1], a2, a3);
            ((float4*)o)[k] = make_float4(a0, a1, a2, a3);
        }
    }
    if (half == 0) {
        g_pz[(sbase + bn + i0) * HE + h]     = z0;
        g_pz[(sbase + bn + i0 + 1) * HE + h] = z1;
    }
}

// ---------------- K5: combine 4 partials + normalize ----------------
__global__ __launch_bounds__(256) void k_reduce(float* __restrict__ out) {
    int idx = blockIdx.x * 256 + threadIdx.x;
    int row = idx >> 5, q = idx & 31;
    int h = q >> 3;

    float z = 0.f;
#pragma unroll
    for (int s = 0; s < SPLIT; ++s)
        z += g_pz[((size_t)s * BB * NN + row) * HE + h];

    float4 acc = make_float4(0.f, 0.f, 0.f, 0.f);
#pragma unroll
    for (int s = 0; s < SPLIT; ++s) {
        float4 v = *(const float4*)&g_pacc[((size_t)s * BB * NN + row) * 128 + q * 4];
        acc.x += v.x; acc.y += v.y; acc.z += v.z; acc.w += v.w;
    }
    float rz = 1.0f / z;
    ((float4*)out)[idx] = make_float4(acc.x * rz, acc.y * rz, acc.z * rz, acc.w * rz);
}

// ---------------- launch ----------------
extern "C" void kernel_launch(void* const* d_in, const int* in_sizes, int n_in,
                              void* d_out, int out_size) {
    const float* h = nullptr;
    const int*   A = nullptr;
    const float* W = nullptr;
    const float* a = nullptr;
    for (int i = 0; i < n_in; ++i) {
        switch (in_sizes[i]) {
            case BB * NN * 128:      h = (const float*)d_in[i]; break;
            case 128 * 128:          W = (const float*)d_in[i]; break;
            case 2 * HD:             a = (const float*)d_in[i]; break;
            default:                 A = (const int*)d_in[i];   break;
        }
    }
    float* out = (float*)d_out;

    k_mm    <<<(BB * NN) / 64, 256>>>(h, W);
    k_params<<<(BB * NN * HE) / 256, 256>>>(a);
    k_pack  <<<4096, 256>>>(A);
    k_attn  <<<BB * (NN / 32) * SPLIT, 128>>>();
    k_reduce<<<(BB * NN * 32) / 256, 256>>>(out);
}

// round 13
// speedup vs baseline: 1.3614x; 1.1076x over previous
#include <cuda_runtime.h>
#include <cstdint>
#include <cstddef>

#define BB 8
#define NN 2048
#define HE 4
#define HD 32
#define SPLIT 4
#define NCH ((NN / SPLIT) / 32)      // 16 chunks of 32 j per CTA

typedef unsigned long long ull;

// ---------------- device scratch ----------------
__device__ float    g_Wh[BB * NN * 128];            // 8 MB
__device__ float2   g_ip2[BB * NN * HE];            // 512KB {e^s, e^{0.2s}}
__device__ float2   g_jp2[BB * NN * HE];            // 512KB {e^t, e^{0.2t}}
__device__ unsigned g_Ab[BB * NN * (NN / 32)];      // 4 MB  packed adjacency
__device__ float    g_pacc[SPLIT * BB * NN * 128];  // 33.5MB unnormalized partials
__device__ float    g_pz[SPLIT * BB * NN * HE];     // 1 MB  partial row sums

// ---------------- helpers ----------------
__device__ __forceinline__ ull packf2(float lo, float hi) {
    ull r; asm("mov.b64 %0,{%1,%2};" : "=l"(r) : "f"(lo), "f"(hi)); return r;
}
__device__ __forceinline__ void unpackf2(ull v, float& lo, float& hi) {
    asm("mov.b64 {%0,%1},%2;" : "=f"(lo), "=f"(hi) : "l"(v));
}

// ---------------- K1: Wh = h @ W ----------------
__global__ __launch_bounds__(256) void k_mm(const float* __restrict__ hmat,
                                            const float* __restrict__ W) {
    __shared__ float hs[64 * 36];
    __shared__ float Ws[32 * 128];
    int tid = threadIdx.x;
    int tx = tid & 15, ty = tid >> 4;
    int rbase = blockIdx.x * 64;

    float acc[4][8];
#pragma unroll
    for (int i = 0; i < 4; ++i)
#pragma unroll
        for (int j = 0; j < 8; ++j) acc[i][j] = 0.f;

    for (int k0 = 0; k0 < 128; k0 += 32) {
        __syncthreads();
#pragma unroll
        for (int m = 0; m < 2; ++m) {
            int idx = tid * 2 + m;
            int r = idx >> 3, q = idx & 7;
            *(float4*)(hs + r * 36 + q * 4) =
                *(const float4*)(hmat + (size_t)(rbase + r) * 128 + k0 + q * 4);
        }
#pragma unroll
        for (int m = 0; m < 4; ++m) {
            int idx = tid + 256 * m;
            int kk = idx >> 5, c4 = idx & 31;
            *(float4*)(Ws + kk * 128 + c4 * 4) =
                *(const float4*)(W + (size_t)(k0 + kk) * 128 + c4 * 4);
        }
        __syncthreads();
#pragma unroll
        for (int kk = 0; kk < 32; ++kk) {
            float av[4], bv[8];
#pragma unroll
            for (int i = 0; i < 4; ++i) av[i] = hs[(ty * 4 + i) * 36 + kk];
#pragma unroll
            for (int j = 0; j < 8; ++j) bv[j] = Ws[kk * 128 + tx + 16 * j];
#pragma unroll
            for (int i = 0; i < 4; ++i)
#pragma unroll
                for (int j = 0; j < 8; ++j) acc[i][j] += av[i] * bv[j];
        }
    }
#pragma unroll
    for (int i = 0; i < 4; ++i)
#pragma unroll
        for (int j = 0; j < 8; ++j)
            g_Wh[(size_t)(rbase + ty * 4 + i) * 128 + tx + 16 * j] = acc[i][j];
}

// ---------------- K2: per-(node,head) params ----------------
__global__ __launch_bounds__(256) void k_params(const float* __restrict__ a) {
    __shared__ float sa[64];
    int tid = threadIdx.x;
    if (tid < 64) sa[tid] = a[tid];
    __syncthreads();
    int idx = blockIdx.x * 256 + tid;
    int nh = idx >> 2, hh = idx & 3;
    const float4* wh = (const float4*)(g_Wh + (size_t)nh * 128 + hh * 32);
    float s = 0.f, t = 0.f;
#pragma unroll
    for (int k = 0; k < 8; ++k) {
        float4 w = wh[k];
        s += w.x * sa[4 * k + 0] + w.y * sa[4 * k + 1] + w.z * sa[4 * k + 2] + w.w * sa[4 * k + 3];
        t += w.x * sa[32 + 4 * k + 0] + w.y * sa[32 + 4 * k + 1] + w.z * sa[32 + 4 * k + 2] + w.w * sa[32 + 4 * k + 3];
    }
    g_ip2[idx] = make_float2(expf(s), expf(0.2f * s));
    g_jp2[idx] = make_float2(expf(t), expf(0.2f * t));
}

// ---------------- K3: pack A into bitmasks ----------------
__global__ __launch_bounds__(256) void k_pack(const int* __restrict__ A) {
    int gt = blockIdx.x * 256 + threadIdx.x;
    int warpId = gt >> 5, lane = gt & 31;
    const int* src = A + (size_t)warpId * 1024;
    unsigned keep = 0;
#pragma unroll
    for (int g = 0; g < 32; ++g) {
        int v = src[g * 32 + lane];
        unsigned m = __ballot_sync(0xffffffffu, v > 0);
        if (g == lane) keep = m;
    }
    g_Ab[(size_t)warpId * 32 + lane] = keep;
}

// ---------------- K4: fused attention, j-split x4, 4-row register blocking --
// CTA = (split, batch, 64-row i-block); 128 threads; grid 1024; 3 CTAs/SM.
// thread = 4 rows x 16 dims -> each shared Wh load feeds 64 MACs (2x round 12),
// 4 independent accumulator chains for latency tolerance.
// Staging machinery identical to round-12 proven kernel.
__global__ __launch_bounds__(128, 3) void k_attn() {
    constexpr int JC = 32;
    __shared__ float  sWh[2][JC * 128];     // 16 KB per buffer
    __shared__ float2 sJP[2][JC * HE];      // 1 KB per buffer

    int tid = threadIdx.x;
    int sp = blockIdx.x & 3;                  // j-split id
    int blk = blockIdx.x >> 2;
    int b = blk >> 5;                         // 32 i-blocks of 64 rows
    int ibase = (blk & 31) << 6;
    int il = tid & 15, hh = tid >> 4;
    int h = hh >> 1, half = hh & 1;
    int i0 = ibase + il * 4;                  // 4 consecutive rows per thread
    int dimoff = h * 32 + half * 16;
    size_t bn = (size_t)b * NN;
    int c0 = sp * NCH;                        // first absolute 32-j chunk

    float2 e0 = g_ip2[(bn + i0 + 0) * 4 + h];
    float2 e1 = g_ip2[(bn + i0 + 1) * 4 + h];
    float2 e2 = g_ip2[(bn + i0 + 2) * 4 + h];
    float2 e3 = g_ip2[(bn + i0 + 3) * 4 + h];

    const float4*   gWh4 = (const float4*)(g_Wh + bn * 128);
    const float2*   gJP  = g_jp2 + bn * 4;
    const unsigned* gA0  = g_Ab + (bn + i0) * 64;
    const unsigned* gA1  = gA0 + 64;
    const unsigned* gA2  = gA0 + 128;
    const unsigned* gA3  = gA0 + 192;

    ull acc[4][8];
#pragma unroll
    for (int r = 0; r < 4; ++r)
#pragma unroll
        for (int k = 0; k < 8; ++k) acc[r][k] = 0ull;
    float z0 = 0.f, z1 = 0.f, z2 = 0.f, z3 = 0.f;

    // prime chunk c0 (32 nodes x 128 dims = 1024 float4; 8 per thread)
#pragma unroll
    for (int m = 0; m < 8; ++m)
        ((float4*)sWh[0])[tid + 128 * m] = gWh4[(size_t)c0 * JC * 32 + tid + 128 * m];
    sJP[0][tid] = gJP[(size_t)c0 * JC * 4 + tid];
    unsigned wa0 = gA0[c0], wa1 = gA1[c0], wa2 = gA2[c0], wa3 = gA3[c0];
    __syncthreads();

    for (int c = 0; c < NCH; ++c) {
        int cur = c & 1, nxt = cur ^ 1;
        float4 r[8]; float2 rj;
        unsigned na0 = 0, na1 = 0, na2 = 0, na3 = 0;
        bool more = (c + 1 < NCH);
        if (more) {   // prefetch next chunk into registers (hides L2 latency)
            const float4* src = gWh4 + (size_t)(c0 + c + 1) * JC * 32;
#pragma unroll
            for (int m = 0; m < 8; ++m) r[m] = src[tid + 128 * m];
            rj  = gJP[(size_t)(c0 + c + 1) * JC * 4 + tid];
            na0 = gA0[c0 + c + 1];
            na1 = gA1[c0 + c + 1];
            na2 = gA2[c0 + c + 1];
            na3 = gA3[c0 + c + 1];
        }

        int m0 = (int)__brev(wa0), m1 = (int)__brev(wa1);
        int m2 = (int)__brev(wa2), m3 = (int)__brev(wa3);
        const float*  whc = sWh[cur];
        const float2* jpc = sJP[cur];

#pragma unroll 4
        for (int jj = 0; jj < JC; ++jj) {
            float2 jp = jpc[jj * 4 + h];                 // {u_j, v_j}
            float p0 = fmaxf(e0.x * jp.x, e0.y * jp.y);  // exp(leakyrelu(s+t))
            float p1 = fmaxf(e1.x * jp.x, e1.y * jp.y);
            float p2 = fmaxf(e2.x * jp.x, e2.y * jp.y);
            float p3 = fmaxf(e3.x * jp.x, e3.y * jp.y);
            p0 = (m0 < 0) ? p0 : 0.0f;                   // adjacency bit (MSB-first)
            p1 = (m1 < 0) ? p1 : 0.0f;
            p2 = (m2 < 0) ? p2 : 0.0f;
            p3 = (m3 < 0) ? p3 : 0.0f;
            m0 <<= 1; m1 <<= 1; m2 <<= 1; m3 <<= 1;
            z0 += p0; z1 += p1; z2 += p2; z3 += p3;

            ull P0 = packf2(p0, p0);
            ull P1 = packf2(p1, p1);
            ull P2 = packf2(p2, p2);
            ull P3 = packf2(p3, p3);

            const float4* wr = (const float4*)&whc[jj * 128 + dimoff];
#pragma unroll
            for (int k = 0; k < 4; ++k) {
                ulonglong2 w = *reinterpret_cast<const ulonglong2*>(wr + k);
                asm("fma.rn.f32x2 %0, %1, %2, %0;" : "+l"(acc[0][2 * k])     : "l"(w.x), "l"(P0));
                asm("fma.rn.f32x2 %0, %1, %2, %0;" : "+l"(acc[0][2 * k + 1]) : "l"(w.y), "l"(P0));
                asm("fma.rn.f32x2 %0, %1, %2, %0;" : "+l"(acc[1][2 * k])     : "l"(w.x), "l"(P1));
                asm("fma.rn.f32x2 %0, %1, %2, %0;" : "+l"(acc[1][2 * k + 1]) : "l"(w.y), "l"(P1));
                asm("fma.rn.f32x2 %0, %1, %2, %0;" : "+l"(acc[2][2 * k])     : "l"(w.x), "l"(P2));
                asm("fma.rn.f32x2 %0, %1, %2, %0;" : "+l"(acc[2][2 * k + 1]) : "l"(w.y), "l"(P2));
                asm("fma.rn.f32x2 %0, %1, %2, %0;" : "+l"(acc[3][2 * k])     : "l"(w.x), "l"(P3));
                asm("fma.rn.f32x2 %0, %1, %2, %0;" : "+l"(acc[3][2 * k + 1]) : "l"(w.y), "l"(P3));
            }
        }

        if (more) {   // write prefetched data into the other buffer
#pragma unroll
            for (int m = 0; m < 8; ++m)
                ((float4*)sWh[nxt])[tid + 128 * m] = r[m];
            sJP[nxt][tid] = rj;
        }
        wa0 = na0; wa1 = na1; wa2 = na2; wa3 = na3;
        __syncthreads();
    }

    // epilogue: store UNNORMALIZED partials + partial z
    size_t sbase = (size_t)sp * BB * NN;
#pragma unroll
    for (int r = 0; r < 4; ++r) {
        float* o = g_pacc + (sbase + bn + i0 + r) * 128 + dimoff;
#pragma unroll
        for (int k = 0; k < 4; ++k) {
            float a0, a1, a2, a3;
            unpackf2(acc[r][2 * k],     a0, a1);
            unpackf2(acc[r][2 * k + 1], a2, a3);
            ((float4*)o)[k] = make_float4(a0, a1, a2, a3);
        }
    }
    if (half == 0) {
        g_pz[(sbase + bn + i0 + 0) * HE + h] = z0;
        g_pz[(sbase + bn + i0 + 1) * HE + h] = z1;
        g_pz[(sbase + bn + i0 + 2) * HE + h] = z2;
        g_pz[(sbase + bn + i0 + 3) * HE + h] = z3;
    }
}

// ---------------- K5: combine 4 partials + normalize ----------------
__global__ __launch_bounds__(256) void k_reduce(float* __restrict__ out) {
    int idx = blockIdx.x * 256 + threadIdx.x;
    int row = idx >> 5, q = idx & 31;
    int h = q >> 3;

    float z = 0.f;
#pragma unroll
    for (int s = 0; s < SPLIT; ++s)
        z += g_pz[((size_t)s * BB * NN + row) * HE + h];

    float4 acc = make_float4(0.f, 0.f, 0.f, 0.f);
#pragma unroll
    for (int s = 0; s < SPLIT; ++s) {
        float4 v = *(const float4*)&g_pacc[((size_t)s * BB * NN + row) * 128 + q * 4];
        acc.x += v.x; acc.y += v.y; acc.z += v.z; acc.w += v.w;
    }
    float rz = 1.0f / z;
    ((float4*)out)[idx] = make_float4(acc.x * rz, acc.y * rz, acc.z * rz, acc.w * rz);
}

// ---------------- launch ----------------
extern "C" void kernel_launch(void* const* d_in, const int* in_sizes, int n_in,
                              void* d_out, int out_size) {
    const float* h = nullptr;
    const int*   A = nullptr;
    const float* W = nullptr;
    const float* a = nullptr;
    for (int i = 0; i < n_in; ++i) {
        switch (in_sizes[i]) {
            case BB * NN * 128:      h = (const float*)d_in[i]; break;
            case 128 * 128:          W = (const float*)d_in[i]; break;
            case 2 * HD:             a = (const float*)d_in[i]; break;
            default:                 A = (const int*)d_in[i];   break;
        }
    }
    float* out = (float*)d_out;

    k_mm    <<<(BB * NN) / 64, 256>>>(h, W);
    k_params<<<(BB * NN * HE) / 256, 256>>>(a);
    k_pack  <<<4096, 256>>>(A);
    k_attn  <<<BB * (NN / 64) * SPLIT, 128>>>();
    k_reduce<<<(BB * NN * 32) / 256, 256>>>(out);
}

// round 14
// speedup vs baseline: 1.3917x; 1.0222x over previous
#include <cuda_runtime.h>
#include <cstdint>
#include <cstddef>

#define BB 8
#define NN 2048
#define HE 4
#define HD 32
#define SPLIT 4
#define NCH ((NN / SPLIT) / 32)      // 16 chunks of 32 j per CTA

typedef unsigned long long ull;

// ---------------- device scratch ----------------
__device__ float    g_Wh[BB * NN * 128];            // 8 MB
__device__ float2   g_ip2[BB * NN * HE];            // 512KB {e^s, e^{0.2s}}
__device__ float2   g_jp2[BB * NN * HE];            // 512KB {e^t, e^{0.2t}}
__device__ unsigned g_Ab[BB * NN * (NN / 32)];      // 4 MB  packed adjacency
__device__ float    g_pacc[SPLIT * BB * NN * 128];  // 33.5MB unnormalized partials
__device__ float    g_pz[SPLIT * BB * NN * HE];     // 1 MB  partial row sums

// ---------------- helpers ----------------
__device__ __forceinline__ ull packf2(float lo, float hi) {
    ull r; asm("mov.b64 %0,{%1,%2};" : "=l"(r) : "f"(lo), "f"(hi)); return r;
}
__device__ __forceinline__ void unpackf2(ull v, float& lo, float& hi) {
    asm("mov.b64 {%0,%1},%2;" : "=f"(lo), "=f"(hi) : "l"(v));
}
__device__ __forceinline__ void cpa16(void* dst, const void* src) {
    unsigned d = (unsigned)__cvta_generic_to_shared(dst);
    asm volatile("cp.async.cg.shared.global [%0], [%1], 16;" :: "r"(d), "l"(src));
}
__device__ __forceinline__ void cpa8(void* dst, const void* src) {
    unsigned d = (unsigned)__cvta_generic_to_shared(dst);
    asm volatile("cp.async.ca.shared.global [%0], [%1], 8;" :: "r"(d), "l"(src));
}
__device__ __forceinline__ void cpcommit() { asm volatile("cp.async.commit_group;"); }
__device__ __forceinline__ void cpwait0()  { asm volatile("cp.async.wait_group 0;"); }

// ---------------- K1: Wh = h @ W ----------------
__global__ __launch_bounds__(256) void k_mm(const float* __restrict__ hmat,
                                            const float* __restrict__ W) {
    __shared__ float hs[64 * 36];
    __shared__ float Ws[32 * 128];
    int tid = threadIdx.x;
    int tx = tid & 15, ty = tid >> 4;
    int rbase = blockIdx.x * 64;

    float acc[4][8];
#pragma unroll
    for (int i = 0; i < 4; ++i)
#pragma unroll
        for (int j = 0; j < 8; ++j) acc[i][j] = 0.f;

    for (int k0 = 0; k0 < 128; k0 += 32) {
        __syncthreads();
#pragma unroll
        for (int m = 0; m < 2; ++m) {
            int idx = tid * 2 + m;
            int r = idx >> 3, q = idx & 7;
            *(float4*)(hs + r * 36 + q * 4) =
                *(const float4*)(hmat + (size_t)(rbase + r) * 128 + k0 + q * 4);
        }
#pragma unroll
        for (int m = 0; m < 4; ++m) {
            int idx = tid + 256 * m;
            int kk = idx >> 5, c4 = idx & 31;
            *(float4*)(Ws + kk * 128 + c4 * 4) =
                *(const float4*)(W + (size_t)(k0 + kk) * 128 + c4 * 4);
        }
        __syncthreads();
#pragma unroll
        for (int kk = 0; kk < 32; ++kk) {
            float av[4], bv[8];
#pragma unroll
            for (int i = 0; i < 4; ++i) av[i] = hs[(ty * 4 + i) * 36 + kk];
#pragma unroll
            for (int j = 0; j < 8; ++j) bv[j] = Ws[kk * 128 + tx + 16 * j];
#pragma unroll
            for (int i = 0; i < 4; ++i)
#pragma unroll
                for (int j = 0; j < 8; ++j) acc[i][j] += av[i] * bv[j];
        }
    }
#pragma unroll
    for (int i = 0; i < 4; ++i)
#pragma unroll
        for (int j = 0; j < 8; ++j)
            g_Wh[(size_t)(rbase + ty * 4 + i) * 128 + tx + 16 * j] = acc[i][j];
}

// ---------------- K2: per-(node,head) params ----------------
__global__ __launch_bounds__(256) void k_params(const float* __restrict__ a) {
    __shared__ float sa[64];
    int tid = threadIdx.x;
    if (tid < 64) sa[tid] = a[tid];
    __syncthreads();
    int idx = blockIdx.x * 256 + tid;
    int nh = idx >> 2, hh = idx & 3;
    const float4* wh = (const float4*)(g_Wh + (size_t)nh * 128 + hh * 32);
    float s = 0.f, t = 0.f;
#pragma unroll
    for (int k = 0; k < 8; ++k) {
        float4 w = wh[k];
        s += w.x * sa[4 * k + 0] + w.y * sa[4 * k + 1] + w.z * sa[4 * k + 2] + w.w * sa[4 * k + 3];
        t += w.x * sa[32 + 4 * k + 0] + w.y * sa[32 + 4 * k + 1] + w.z * sa[32 + 4 * k + 2] + w.w * sa[32 + 4 * k + 3];
    }
    g_ip2[idx] = make_float2(expf(s), expf(0.2f * s));
    g_jp2[idx] = make_float2(expf(t), expf(0.2f * t));
}

// ---------------- K3: pack A into bitmasks ----------------
__global__ __launch_bounds__(256) void k_pack(const int* __restrict__ A) {
    int gt = blockIdx.x * 256 + threadIdx.x;
    int warpId = gt >> 5, lane = gt & 31;
    const int* src = A + (size_t)warpId * 1024;
    unsigned keep = 0;
#pragma unroll
    for (int g = 0; g < 32; ++g) {
        int v = src[g * 32 + lane];
        unsigned m = __ballot_sync(0xffffffffu, v > 0);
        if (g == lane) keep = m;
    }
    g_Ab[(size_t)warpId * 32 + lane] = keep;
}

// ---------------- K4: fused attention ------------------------------------
// CTA = (split, batch, 64-row i-block); 128 threads; grid 1024; 4 CTAs/SM.
// thread = 2 rows x 32 dims (ONE FULL HEAD); warp = 32 il-threads, same h
//   -> every Wh LDS.128 is a uniform-address 32-lane broadcast (conflict-free)
//   -> p-gen computed once per (i,h) instead of twice (round-13 halves).
// Staging: 2-stage cp.async pipeline at distance 1, ONE barrier per chunk:
//   iter c: wait_group0 (chunk c arrived; issued last iter), barrier,
//           issue chunk c+1 into buf nxt (consumed at c-1, fenced by barrier),
//           commit, consume buf cur.
__global__ __launch_bounds__(128, 4) void k_attn() {
    constexpr int JC = 32;
    __shared__ float  sWh[2][JC * 128];     // 16 KB per buffer
    __shared__ float2 sJP[2][JC * HE];      // 1 KB per buffer

    int tid = threadIdx.x;
    int sp = blockIdx.x & 3;                  // j-split id
    int blk = blockIdx.x >> 2;
    int b = blk >> 5;                         // 32 i-blocks of 64 rows
    int ibase = (blk & 31) << 6;
    int h = tid >> 5;                         // warp id == head
    int il = tid & 31;
    int i0 = ibase + il * 2;                  // 2 consecutive rows per thread
    int dimoff = h * 32;
    size_t bn = (size_t)b * NN;
    int c0 = sp * NCH;                        // first absolute 32-j chunk

    float2 e0 = g_ip2[(bn + i0 + 0) * 4 + h];
    float2 e1 = g_ip2[(bn + i0 + 1) * 4 + h];

    const float4*   gWh4 = (const float4*)(g_Wh + bn * 128);
    const float2*   gJP  = g_jp2 + bn * 4;
    const unsigned* gA0  = g_Ab + (bn + i0) * 64;
    const unsigned* gA1  = gA0 + 64;

    ull acc[2][16];
#pragma unroll
    for (int r = 0; r < 2; ++r)
#pragma unroll
        for (int k = 0; k < 16; ++k) acc[r][k] = 0ull;
    float z0 = 0.f, z1 = 0.f;

    // prologue: issue chunk c0 into buf 0
    {
        const float4* src = gWh4 + (size_t)c0 * JC * 32;
#pragma unroll
        for (int m = 0; m < 8; ++m)
            cpa16(&((float4*)sWh[0])[tid + 128 * m], src + tid + 128 * m);
        cpa8(&sJP[0][tid], gJP + (size_t)c0 * JC * 4 + tid);
        cpcommit();
    }
    unsigned wa0 = gA0[c0], wa1 = gA1[c0];

    for (int c = 0; c < NCH; ++c) {
        cpwait0();                  // chunk c arrived (issued previous iter)
        __syncthreads();            // visible to all; also fences buf nxt reads
        int cur = c & 1, nxt = cur ^ 1;

        unsigned na0 = 0, na1 = 0;
        if (c + 1 < NCH) {          // issue chunk c+1 into buf nxt
            const float4* src = gWh4 + (size_t)(c0 + c + 1) * JC * 32;
#pragma unroll
            for (int m = 0; m < 8; ++m)
                cpa16(&((float4*)sWh[nxt])[tid + 128 * m], src + tid + 128 * m);
            cpa8(&sJP[nxt][tid], gJP + (size_t)(c0 + c + 1) * JC * 4 + tid);
            na0 = gA0[c0 + c + 1];
            na1 = gA1[c0 + c + 1];
        }
        cpcommit();                 // one group per iter (possibly empty)

        int m0 = (int)__brev(wa0), m1 = (int)__brev(wa1);
        const float*  whc = sWh[cur];
        const float2* jpc = sJP[cur];

#pragma unroll 4
        for (int jj = 0; jj < JC; ++jj) {
            float2 jp = jpc[jj * 4 + h];                 // {u_j, v_j}  warp-uniform
            float p0 = fmaxf(e0.x * jp.x, e0.y * jp.y);  // exp(leakyrelu(s+t))
            float p1 = fmaxf(e1.x * jp.x, e1.y * jp.y);
            p0 = (m0 < 0) ? p0 : 0.0f;                   // adjacency bit (MSB-first)
            p1 = (m1 < 0) ? p1 : 0.0f;
            m0 <<= 1; m1 <<= 1;
            z0 += p0; z1 += p1;

            ull P0 = packf2(p0, p0);
            ull P1 = packf2(p1, p1);

            const float4* wr = (const float4*)&whc[jj * 128 + dimoff];  // uniform addr
#pragma unroll
            for (int k = 0; k < 8; ++k) {
                ulonglong2 w = *reinterpret_cast<const ulonglong2*>(wr + k);
                asm("fma.rn.f32x2 %0, %1, %2, %0;" : "+l"(acc[0][2 * k])     : "l"(w.x), "l"(P0));
                asm("fma.rn.f32x2 %0, %1, %2, %0;" : "+l"(acc[0][2 * k + 1]) : "l"(w.y), "l"(P0));
                asm("fma.rn.f32x2 %0, %1, %2, %0;" : "+l"(acc[1][2 * k])     : "l"(w.x), "l"(P1));
                asm("fma.rn.f32x2 %0, %1, %2, %0;" : "+l"(acc[1][2 * k + 1]) : "l"(w.y), "l"(P1));
            }
        }
        wa0 = na0; wa1 = na1;
    }

    // epilogue: store UNNORMALIZED partials + partial z
    size_t sbase = (size_t)sp * BB * NN;
#pragma unroll
    for (int r = 0; r < 2; ++r) {
        float* o = g_pacc + (sbase + bn + i0 + r) * 128 + dimoff;
#pragma unroll
        for (int k = 0; k < 8; ++k) {
            float a0, a1, a2, a3;
            unpackf2(acc[r][2 * k],     a0, a1);
            unpackf2(acc[r][2 * k + 1], a2, a3);
            ((float4*)o)[k] = make_float4(a0, a1, a2, a3);
        }
    }
    g_pz[(sbase + bn + i0 + 0) * HE + h] = z0;
    g_pz[(sbase + bn + i0 + 1) * HE + h] = z1;
}

// ---------------- K5: combine 4 partials + normalize ----------------
__global__ __launch_bounds__(256) void k_reduce(float* __restrict__ out) {
    int idx = blockIdx.x * 256 + threadIdx.x;
    int row = idx >> 5, q = idx & 31;
    int h = q >> 3;

    float z = 0.f;
#pragma unroll
    for (int s = 0; s < SPLIT; ++s)
        z += g_pz[((size_t)s * BB * NN + row) * HE + h];

    float4 acc = make_float4(0.f, 0.f, 0.f, 0.f);
#pragma unroll
    for (int s = 0; s < SPLIT; ++s) {
        float4 v = *(const float4*)&g_pacc[((size_t)s * BB * NN + row) * 128 + q * 4];
        acc.x += v.x; acc.y += v.y; acc.z += v.z; acc.w += v.w;
    }
    float rz = 1.0f / z;
    ((float4*)out)[idx] = make_float4(acc.x * rz, acc.y * rz, acc.z * rz, acc.w * rz);
}

// ---------------- launch ----------------
extern "C" void kernel_launch(void* const* d_in, const int* in_sizes, int n_in,
                              void* d_out, int out_size) {
    const float* h = nullptr;
    const int*   A = nullptr;
    const float* W = nullptr;
    const float* a = nullptr;
    for (int i = 0; i < n_in; ++i) {
        switch (in_sizes[i]) {
            case BB * NN * 128:      h = (const float*)d_in[i]; break;
            case 128 * 128:          W = (const float*)d_in[i]; break;
            case 2 * HD:             a = (const float*)d_in[i]; break;
            default:                 A = (const int*)d_in[i];   break;
        }
    }
    float* out = (float*)d_out;

    k_mm    <<<(BB * NN) / 64, 256>>>(h, W);
    k_params<<<(BB * NN * HE) / 256, 256>>>(a);
    k_pack  <<<4096, 256>>>(A);
    k_attn  <<<BB * (NN / 64) * SPLIT, 128>>>();
    k_reduce<<<(BB * NN * 32) / 256, 256>>>(out);
}

// round 15
// speedup vs baseline: 2.0248x; 1.4549x over previous
#include <cuda_runtime.h>
#include <cstdint>
#include <cstddef>

#define BB 8
#define NN 2048
#define HE 4
#define HD 32
#define SPLIT 4
#define NCH ((NN / SPLIT) / 32)      // 16 chunks of 32 j per CTA
#define WPITCH 132                   // smem row pitch (floats) for bank spread

typedef unsigned long long ull;
typedef unsigned int uint;

// ---------------- device scratch ----------------
__device__ float    g_Wh[BB * NN * 128];            // 8 MB
__device__ float2   g_ip2[BB * NN * HE];            // {e^s, e^{0.2s}}
__device__ float2   g_jp2[BB * NN * HE];            // {e^t, e^{0.2t}}
__device__ unsigned g_Ab[BB * NN * (NN / 32)];      // packed adjacency
__device__ float    g_pacc[SPLIT * BB * NN * 128];  // unnormalized partials
__device__ float    g_pz[SPLIT * BB * NN * HE];     // partial row sums

// ---------------- helpers ----------------
__device__ __forceinline__ ull packu2(uint lo, uint hi) {
    ull r; asm("mov.b64 %0,{%1,%2};" : "=l"(r) : "r"(lo), "r"(hi)); return r;
}
__device__ __forceinline__ ull addx2(ull a, ull b) {
    ull r; asm("add.rn.f32x2 %0,%1,%2;" : "=l"(r) : "l"(a), "l"(b)); return r;
}
__device__ __forceinline__ void unpackf2(ull v, float& lo, float& hi) {
    asm("mov.b64 {%0,%1},%2;" : "=f"(lo), "=f"(hi) : "l"(v));
}
__device__ __forceinline__ uint cvt_tf32(float f) {
    uint u; asm("cvt.rna.tf32.f32 %0, %1;" : "=r"(u) : "f"(f)); return u;
}
__device__ __forceinline__ uint bit_mask1(uint m, int b) {   // bit b -> 0 or 0xffffffff
    uint r; asm("bfe.s32 %0, %1, %2, 1;" : "=r"(r) : "r"(m), "r"(b)); return r;
}
__device__ __forceinline__ void mma8(float* d, uint a0, uint a1, uint a2, uint a3,
                                     uint b0, uint b1) {
    asm("mma.sync.aligned.m16n8k8.row.col.f32.tf32.tf32.f32 "
        "{%0,%1,%2,%3},{%4,%5,%6,%7},{%8,%9},{%0,%1,%2,%3};"
        : "+f"(d[0]), "+f"(d[1]), "+f"(d[2]), "+f"(d[3])
        : "r"(a0), "r"(a1), "r"(a2), "r"(a3), "r"(b0), "r"(b1));
}
__device__ __forceinline__ void cpa16(void* dst, const void* src) {
    unsigned d = (unsigned)__cvta_generic_to_shared(dst);
    asm volatile("cp.async.cg.shared.global [%0], [%1], 16;" :: "r"(d), "l"(src));
}
__device__ __forceinline__ void cpcommit() { asm volatile("cp.async.commit_group;"); }
__device__ __forceinline__ void cpwait0()  { asm volatile("cp.async.wait_group 0;"); }

// ---------------- K1: Wh = h @ W ----------------
__global__ __launch_bounds__(256) void k_mm(const float* __restrict__ hmat,
                                            const float* __restrict__ W) {
    __shared__ float hs[64 * 36];
    __shared__ float Ws[32 * 128];
    int tid = threadIdx.x;
    int tx = tid & 15, ty = tid >> 4;
    int rbase = blockIdx.x * 64;

    float acc[4][8];
#pragma unroll
    for (int i = 0; i < 4; ++i)
#pragma unroll
        for (int j = 0; j < 8; ++j) acc[i][j] = 0.f;

    for (int k0 = 0; k0 < 128; k0 += 32) {
        __syncthreads();
#pragma unroll
        for (int m = 0; m < 2; ++m) {
            int idx = tid * 2 + m;
            int r = idx >> 3, q = idx & 7;
            *(float4*)(hs + r * 36 + q * 4) =
                *(const float4*)(hmat + (size_t)(rbase + r) * 128 + k0 + q * 4);
        }
#pragma unroll
        for (int m = 0; m < 4; ++m) {
            int idx = tid + 256 * m;
            int kk = idx >> 5, c4 = idx & 31;
            *(float4*)(Ws + kk * 128 + c4 * 4) =
                *(const float4*)(W + (size_t)(k0 + kk) * 128 + c4 * 4);
        }
        __syncthreads();
#pragma unroll
        for (int kk = 0; kk < 32; ++kk) {
            float av[4], bv[8];
#pragma unroll
            for (int i = 0; i < 4; ++i) av[i] = hs[(ty * 4 + i) * 36 + kk];
#pragma unroll
            for (int j = 0; j < 8; ++j) bv[j] = Ws[kk * 128 + tx + 16 * j];
#pragma unroll
            for (int i = 0; i < 4; ++i)
#pragma unroll
                for (int j = 0; j < 8; ++j) acc[i][j] += av[i] * bv[j];
        }
    }
#pragma unroll
    for (int i = 0; i < 4; ++i)
#pragma unroll
        for (int j = 0; j < 8; ++j)
            g_Wh[(size_t)(rbase + ty * 4 + i) * 128 + tx + 16 * j] = acc[i][j];
}

// ---------------- K2: per-(node,head) params ----------------
__global__ __launch_bounds__(256) void k_params(const float* __restrict__ a) {
    __shared__ float sa[64];
    int tid = threadIdx.x;
    if (tid < 64) sa[tid] = a[tid];
    __syncthreads();
    int idx = blockIdx.x * 256 + tid;
    int nh = idx >> 2, hh = idx & 3;
    const float4* wh = (const float4*)(g_Wh + (size_t)nh * 128 + hh * 32);
    float s = 0.f, t = 0.f;
#pragma unroll
    for (int k = 0; k < 8; ++k) {
        float4 w = wh[k];
        s += w.x * sa[4 * k + 0] + w.y * sa[4 * k + 1] + w.z * sa[4 * k + 2] + w.w * sa[4 * k + 3];
        t += w.x * sa[32 + 4 * k + 0] + w.y * sa[32 + 4 * k + 1] + w.z * sa[32 + 4 * k + 2] + w.w * sa[32 + 4 * k + 3];
    }
    g_ip2[idx] = make_float2(expf(s), expf(0.2f * s));
    g_jp2[idx] = make_float2(expf(t), expf(0.2f * t));
}

// ---------------- K3: pack A into bitmasks ----------------
__global__ __launch_bounds__(256) void k_pack(const int* __restrict__ A) {
    int gt = blockIdx.x * 256 + threadIdx.x;
    int warpId = gt >> 5, lane = gt & 31;
    const int* src = A + (size_t)warpId * 1024;
    unsigned keep = 0;
#pragma unroll
    for (int g = 0; g < 32; ++g) {
        int v = src[g * 32 + lane];
        unsigned m = __ballot_sync(0xffffffffu, v > 0);
        if (g == lane) keep = m;
    }
    g_Ab[(size_t)warpId * 32 + lane] = keep;
}

// ---------------- K4: fused attention via mma.sync tf32 ---------------------
// CTA = (split, batch, 64-row i-tile); 256 threads = 8 warps = (4 heads x 2
// m-halves). Warp computes out[32 rows, 32 dims] for head h over 512 j's.
// P generated straight into A-fragments (no smem round-trip for P):
//   p = max(E1_i*u_j, E2_i*v_j) masked by adjacency bit, cvt.rna to tf32.
// Fragment maps (m16n8k8.row.col, g=lane>>2, c=lane&3, kf-block = 8 j):
//   A: a0=(g,c) a1=(g+8,c) a2=(g,c+4) a3=(g+8,c+4)   [rows, j-cols]
//   B: b0=(c,g) b1=(c+4,g)                            [j-rows, dim-cols]
//   D: d0=(g,2c) d1=(g,2c+1) d2=(g+8,2c) d3=(g+8,2c+1)
__global__ __launch_bounds__(256, 2) void k_attn() {
    constexpr int JC = 32;
    __shared__ float    sWh[2][JC * WPITCH];   // 33792 B
    __shared__ float2   sJP[2][JC * HE];       // 2048 B
    __shared__ unsigned sMask[64 * 16];        // [row_local][chunk] 4096 B

    int tid = threadIdx.x;
    int warp = tid >> 5, lane = tid & 31;
    int h = warp & 3, mh = warp >> 2;
    int g = lane >> 2, cl = lane & 3;

    int sp = blockIdx.x & 3;
    int blk = blockIdx.x >> 2;
    int b = blk >> 5;
    int ibase = (blk & 31) << 6;               // 64-row i-tile
    size_t bn = (size_t)b * NN;
    int c0 = sp * NCH;                         // first chunk (== mask word idx)

    const float*  gWh = g_Wh + bn * 128;
    const float2* gJP = g_jp2 + bn * 4;

    // per-thread rows (CTA-local): mh*32 + mf*16 + g + 8*i
    int rl0 = mh * 32 + g;
    float2 e[4];
    e[0] = g_ip2[(bn + ibase + rl0 +  0) * 4 + h];
    e[1] = g_ip2[(bn + ibase + rl0 +  8) * 4 + h];
    e[2] = g_ip2[(bn + ibase + rl0 + 16) * 4 + h];
    e[3] = g_ip2[(bn + ibase + rl0 + 24) * 4 + h];

    // preload adjacency words: sMask[r][ch], r<64, ch<16
#pragma unroll
    for (int m = 0; m < 4; ++m) {
        int idx = tid + 256 * m;
        int r = idx >> 4, ch = idx & 15;
        sMask[r * 16 + ch] = g_Ab[(bn + ibase + r) * 64 + c0 + ch];
    }

    float acc[2][4][4];
#pragma unroll
    for (int mf = 0; mf < 2; ++mf)
#pragma unroll
        for (int nf = 0; nf < 4; ++nf)
#pragma unroll
            for (int q = 0; q < 4; ++q) acc[mf][nf][q] = 0.f;
    ull zp[4];
#pragma unroll
    for (int r = 0; r < 4; ++r) zp[r] = 0ull;

    // prologue: stage chunk 0 into buf 0
    {
#pragma unroll
        for (int m = 0; m < 4; ++m) {
            int idx = tid + 256 * m;
            int jl = idx >> 5, q = idx & 31;
            cpa16(&sWh[0][jl * WPITCH + q * 4],
                  gWh + ((size_t)c0 * 32 + jl) * 128 + q * 4);
        }
        if (tid < 64)
            cpa16(&((float4*)sJP[0])[tid],
                  (const float4*)(gJP + (size_t)c0 * JC * 4) + tid);
        cpcommit();
    }

    for (int c = 0; c < NCH; ++c) {
        cpwait0();
        __syncthreads();
        int cur = c & 1, nxt = cur ^ 1;

        if (c + 1 < NCH) {     // stage chunk c+1 into buf nxt
#pragma unroll
            for (int m = 0; m < 4; ++m) {
                int idx = tid + 256 * m;
                int jl = idx >> 5, q = idx & 31;
                cpa16(&sWh[nxt][jl * WPITCH + q * 4],
                      gWh + ((size_t)(c0 + c + 1) * 32 + jl) * 128 + q * 4);
            }
            if (tid < 64)
                cpa16(&((float4*)sJP[nxt])[tid],
                      (const float4*)(gJP + (size_t)(c0 + c + 1) * JC * 4) + tid);
        }
        cpcommit();

        uint mk[4];
        mk[0] = sMask[(rl0 +  0) * 16 + c];
        mk[1] = sMask[(rl0 +  8) * 16 + c];
        mk[2] = sMask[(rl0 + 16) * 16 + c];
        mk[3] = sMask[(rl0 + 24) * 16 + c];

        const float*  whc = sWh[cur];
        const float2* jpc = sJP[cur];

#pragma unroll
        for (int kf = 0; kf < 4; ++kf) {
            int jl0 = 8 * kf + cl, jl1 = jl0 + 4;
            float2 ua = jpc[jl0 * 4 + h];              // {u, v} at j = jl0
            float2 ub = jpc[jl1 * 4 + h];

            uint b0[4], b1[4];
#pragma unroll
            for (int nf = 0; nf < 4; ++nf) {
                b0[nf] = cvt_tf32(whc[jl0 * WPITCH + h * 32 + nf * 8 + g]);
                b1[nf] = cvt_tf32(whc[jl1 * WPITCH + h * 32 + nf * 8 + g]);
            }

#pragma unroll
            for (int mf = 0; mf < 2; ++mf) {
                float2 eA = e[2 * mf], eB = e[2 * mf + 1];
                uint mA = mk[2 * mf], mB = mk[2 * mf + 1];
                float pv00 = fmaxf(eA.x * ua.x, eA.y * ua.y);   // (r0, jl0)
                float pv10 = fmaxf(eB.x * ua.x, eB.y * ua.y);   // (r1, jl0)
                float pv01 = fmaxf(eA.x * ub.x, eA.y * ub.y);   // (r0, jl1)
                float pv11 = fmaxf(eB.x * ub.x, eB.y * ub.y);   // (r1, jl1)
                uint a0 = cvt_tf32(pv00) & bit_mask1(mA, jl0);
                uint a1 = cvt_tf32(pv10) & bit_mask1(mB, jl0);
                uint a2 = cvt_tf32(pv01) & bit_mask1(mA, jl1);
                uint a3 = cvt_tf32(pv11) & bit_mask1(mB, jl1);
                zp[2 * mf]     = addx2(zp[2 * mf],     packu2(a0, a2));  // row r0
                zp[2 * mf + 1] = addx2(zp[2 * mf + 1], packu2(a1, a3));  // row r1
#pragma unroll
                for (int nf = 0; nf < 4; ++nf)
                    mma8(acc[mf][nf], a0, a1, a2, a3, b0[nf], b1[nf]);
            }
        }
    }

    // ---- z: per-row sums, reduce over the 4 c-lanes sharing each row ----
    float z[4];
#pragma unroll
    for (int r = 0; r < 4; ++r) {
        float lo, hi; unpackf2(zp[r], lo, hi);
        z[r] = lo + hi;
        z[r] += __shfl_xor_sync(0xffffffffu, z[r], 1);
        z[r] += __shfl_xor_sync(0xffffffffu, z[r], 2);
    }
    size_t sbase = (size_t)sp * BB * NN;
    if (cl == 0) {
        g_pz[(sbase + bn + ibase + rl0 +  0) * HE + h] = z[0];
        g_pz[(sbase + bn + ibase + rl0 +  8) * HE + h] = z[1];
        g_pz[(sbase + bn + ibase + rl0 + 16) * HE + h] = z[2];
        g_pz[(sbase + bn + ibase + rl0 + 24) * HE + h] = z[3];
    }

    // ---- store unnormalized partial accumulators ----
#pragma unroll
    for (int mf = 0; mf < 2; ++mf) {
        int row0 = ibase + mh * 32 + mf * 16 + g;
        int row1 = row0 + 8;
#pragma unroll
        for (int nf = 0; nf < 4; ++nf) {
            int dim = h * 32 + nf * 8 + 2 * cl;
            *(float2*)&g_pacc[(sbase + bn + row0) * 128 + dim] =
                make_float2(acc[mf][nf][0], acc[mf][nf][1]);
            *(float2*)&g_pacc[(sbase + bn + row1) * 128 + dim] =
                make_float2(acc[mf][nf][2], acc[mf][nf][3]);
        }
    }
}

// ---------------- K5: combine 4 partials + normalize ----------------
__global__ __launch_bounds__(256) void k_reduce(float* __restrict__ out) {
    int idx = blockIdx.x * 256 + threadIdx.x;
    int row = idx >> 5, q = idx & 31;
    int h = q >> 3;

    float z = 0.f;
#pragma unroll
    for (int s = 0; s < SPLIT; ++s)
        z += g_pz[((size_t)s * BB * NN + row) * HE + h];

    float4 acc = make_float4(0.f, 0.f, 0.f, 0.f);
#pragma unroll
    for (int s = 0; s < SPLIT; ++s) {
        float4 v = *(const float4*)&g_pacc[((size_t)s * BB * NN + row) * 128 + q * 4];
        acc.x += v.x; acc.y += v.y; acc.z += v.z; acc.w += v.w;
    }
    float rz = 1.0f / z;
    ((float4*)out)[idx] = make_float4(acc.x * rz, acc.y * rz, acc.z * rz, acc.w * rz);
}

// ---------------- launch ----------------
extern "C" void kernel_launch(void* const* d_in, const int* in_sizes, int n_in,
                              void* d_out, int out_size) {
    const float* h = nullptr;
    const int*   A = nullptr;
    const float* W = nullptr;
    const float* a = nullptr;
    for (int i = 0; i < n_in; ++i) {
        switch (in_sizes[i]) {
            case BB * NN * 128:      h = (const float*)d_in[i]; break;
            case 128 * 128:          W = (const float*)d_in[i]; break;
            case 2 * HD:             a = (const float*)d_in[i]; break;
            default:                 A = (const int*)d_in[i];   break;
        }
    }
    float* out = (float*)d_out;

    k_mm    <<<(BB * NN) / 64, 256>>>(h, W);
    k_params<<<(BB * NN * HE) / 256, 256>>>(a);
    k_pack  <<<4096, 256>>>(A);
    k_attn  <<<BB * (NN / 64) * SPLIT, 256>>>();
    k_reduce<<<(BB * NN * 32) / 256, 256>>>(out);
}

// round 16
// speedup vs baseline: 2.1706x; 1.0721x over previous
#include <cuda_runtime.h>
#include <cstdint>
#include <cstddef>

#define BB 8
#define NN 2048
#define HE 4
#define HD 32
#define SPLIT 4
#define NCH ((NN / SPLIT) / 32)      // 16 chunks of 32 j per CTA
#define WPITCH 132                   // smem row pitch (floats) for bank spread

typedef unsigned long long ull;
typedef unsigned int uint;

// ---------------- device scratch ----------------
__device__ float    g_Wh[BB * NN * 128];            // 8 MB  full-precision Wh
__device__ float    g_Whr[BB * NN * 128];           // 8 MB  tf32-rounded Wh (mma B operand)
__device__ float2   g_ip2[BB * NN * HE];            // {e^s, e^{0.2s}}
__device__ float2   g_jp2[BB * NN * HE];            // {e^t, e^{0.2t}}
__device__ unsigned g_Ab[BB * NN * (NN / 32)];      // packed adjacency
__device__ float    g_pacc[SPLIT * BB * NN * 128];  // unnormalized partials
__device__ float    g_pz[SPLIT * BB * NN * HE];     // partial row sums

// ---------------- helpers ----------------
__device__ __forceinline__ uint cvt_tf32(float f) {
    uint u; asm("cvt.rna.tf32.f32 %0, %1;" : "=r"(u) : "f"(f)); return u;
}
__device__ __forceinline__ uint bit_mask1(uint m, int b) {   // bit b -> 0 or 0xffffffff
    uint r; asm("bfe.s32 %0, %1, %2, 1;" : "=r"(r) : "r"(m), "r"(b)); return r;
}
__device__ __forceinline__ void mma8(float* d, uint a0, uint a1, uint a2, uint a3,
                                     uint b0, uint b1) {
    asm("mma.sync.aligned.m16n8k8.row.col.f32.tf32.tf32.f32 "
        "{%0,%1,%2,%3},{%4,%5,%6,%7},{%8,%9},{%0,%1,%2,%3};"
        : "+f"(d[0]), "+f"(d[1]), "+f"(d[2]), "+f"(d[3])
        : "r"(a0), "r"(a1), "r"(a2), "r"(a3), "r"(b0), "r"(b1));
}
__device__ __forceinline__ void cpa16(void* dst, const void* src) {
    unsigned d = (unsigned)__cvta_generic_to_shared(dst);
    asm volatile("cp.async.cg.shared.global [%0], [%1], 16;" :: "r"(d), "l"(src));
}
__device__ __forceinline__ void cpcommit() { asm volatile("cp.async.commit_group;"); }
__device__ __forceinline__ void cpwait0()  { asm volatile("cp.async.wait_group 0;"); }

// ---------------- K1: Wh = h @ W  (also emits tf32-rounded copy) ----------
__global__ __launch_bounds__(256) void k_mm(const float* __restrict__ hmat,
                                            const float* __restrict__ W) {
    __shared__ float hs[64 * 36];
    __shared__ float Ws[32 * 128];
    int tid = threadIdx.x;
    int tx = tid & 15, ty = tid >> 4;
    int rbase = blockIdx.x * 64;

    float acc[4][8];
#pragma unroll
    for (int i = 0; i < 4; ++i)
#pragma unroll
        for (int j = 0; j < 8; ++j) acc[i][j] = 0.f;

    for (int k0 = 0; k0 < 128; k0 += 32) {
        __syncthreads();
#pragma unroll
        for (int m = 0; m < 2; ++m) {
            int idx = tid * 2 + m;
            int r = idx >> 3, q = idx & 7;
            *(float4*)(hs + r * 36 + q * 4) =
                *(const float4*)(hmat + (size_t)(rbase + r) * 128 + k0 + q * 4);
        }
#pragma unroll
        for (int m = 0; m < 4; ++m) {
            int idx = tid + 256 * m;
            int kk = idx >> 5, c4 = idx & 31;
            *(float4*)(Ws + kk * 128 + c4 * 4) =
                *(const float4*)(W + (size_t)(k0 + kk) * 128 + c4 * 4);
        }
        __syncthreads();
#pragma unroll
        for (int kk = 0; kk < 32; ++kk) {
            float av[4], bv[8];
#pragma unroll
            for (int i = 0; i < 4; ++i) av[i] = hs[(ty * 4 + i) * 36 + kk];
#pragma unroll
            for (int j = 0; j < 8; ++j) bv[j] = Ws[kk * 128 + tx + 16 * j];
#pragma unroll
            for (int i = 0; i < 4; ++i)
#pragma unroll
                for (int j = 0; j < 8; ++j) acc[i][j] += av[i] * bv[j];
        }
    }
#pragma unroll
    for (int i = 0; i < 4; ++i)
#pragma unroll
        for (int j = 0; j < 8; ++j) {
            size_t idx = (size_t)(rbase + ty * 4 + i) * 128 + tx + 16 * j;
            g_Wh[idx]  = acc[i][j];
            g_Whr[idx] = __uint_as_float(cvt_tf32(acc[i][j]));
        }
}

// ---------------- K2: per-(node,head) params (full-precision Wh) ----------
__global__ __launch_bounds__(256) void k_params(const float* __restrict__ a) {
    __shared__ float sa[64];
    int tid = threadIdx.x;
    if (tid < 64) sa[tid] = a[tid];
    __syncthreads();
    int idx = blockIdx.x * 256 + tid;
    int nh = idx >> 2, hh = idx & 3;
    const float4* wh = (const float4*)(g_Wh + (size_t)nh * 128 + hh * 32);
    float s = 0.f, t = 0.f;
#pragma unroll
    for (int k = 0; k < 8; ++k) {
        float4 w = wh[k];
        s += w.x * sa[4 * k + 0] + w.y * sa[4 * k + 1] + w.z * sa[4 * k + 2] + w.w * sa[4 * k + 3];
        t += w.x * sa[32 + 4 * k + 0] + w.y * sa[32 + 4 * k + 1] + w.z * sa[32 + 4 * k + 2] + w.w * sa[32 + 4 * k + 3];
    }
    g_ip2[idx] = make_float2(expf(s), expf(0.2f * s));
    g_jp2[idx] = make_float2(expf(t), expf(0.2f * t));
}

// ---------------- K3: pack A into bitmasks ----------------
__global__ __launch_bounds__(256) void k_pack(const int* __restrict__ A) {
    int gt = blockIdx.x * 256 + threadIdx.x;
    int warpId = gt >> 5, lane = gt & 31;
    const int* src = A + (size_t)warpId * 1024;
    unsigned keep = 0;
#pragma unroll
    for (int g = 0; g < 32; ++g) {
        int v = src[g * 32 + lane];
        unsigned m = __ballot_sync(0xffffffffu, v > 0);
        if (g == lane) keep = m;
    }
    g_Ab[(size_t)warpId * 32 + lane] = keep;
}

// ---------------- K4: fused attention via mma.sync tf32 ---------------------
// CTA = (split, batch, 64-row i-tile); 256 threads = 8 warps = (4 heads x 2
// m-halves). Warp computes out[32 rows, 32 dims] for head h over 512 j's.
// B operand staged from PRE-ROUNDED g_Whr -> no in-loop cvt on B (ALU cut).
// z accumulated as scalars (no mov.b64 pairing; fma-pipe FADDs).
// Fragment maps (m16n8k8.row.col, g=lane>>2, cl=lane&3, kf-block = 8 j):
//   A: a0=(g,cl) a1=(g+8,cl) a2=(g,cl+4) a3=(g+8,cl+4)  [rows, j-cols]
//   B: b0=(cl,g) b1=(cl+4,g)                             [j-rows, dim-cols]
//   D: d0=(g,2cl) d1=(g,2cl+1) d2=(g+8,2cl) d3=(g+8,2cl+1)
__global__ __launch_bounds__(256, 2) void k_attn() {
    constexpr int JC = 32;
    __shared__ float    sWh[2][JC * WPITCH];   // 33792 B
    __shared__ float2   sJP[2][JC * HE];       // 2048 B
    __shared__ unsigned sMask[64 * 16];        // [row_local][chunk] 4096 B

    int tid = threadIdx.x;
    int warp = tid >> 5, lane = tid & 31;
    int h = warp & 3, mh = warp >> 2;
    int g = lane >> 2, cl = lane & 3;

    int sp = blockIdx.x & 3;
    int blk = blockIdx.x >> 2;
    int b = blk >> 5;
    int ibase = (blk & 31) << 6;               // 64-row i-tile
    size_t bn = (size_t)b * NN;
    int c0 = sp * NCH;                         // first chunk (== mask word idx)

    const float*  gWh = g_Whr + bn * 128;      // pre-rounded values
    const float2* gJP = g_jp2 + bn * 4;

    // per-thread rows (CTA-local): mh*32 + mf*16 + g + 8*i
    int rl0 = mh * 32 + g;
    float2 e[4];
    e[0] = g_ip2[(bn + ibase + rl0 +  0) * 4 + h];
    e[1] = g_ip2[(bn + ibase + rl0 +  8) * 4 + h];
    e[2] = g_ip2[(bn + ibase + rl0 + 16) * 4 + h];
    e[3] = g_ip2[(bn + ibase + rl0 + 24) * 4 + h];

    // preload adjacency words: sMask[r][ch], r<64, ch<16
#pragma unroll
    for (int m = 0; m < 4; ++m) {
        int idx = tid + 256 * m;
        int r = idx >> 4, ch = idx & 15;
        sMask[r * 16 + ch] = g_Ab[(bn + ibase + r) * 64 + c0 + ch];
    }

    float acc[2][4][4];
#pragma unroll
    for (int mf = 0; mf < 2; ++mf)
#pragma unroll
        for (int nf = 0; nf < 4; ++nf)
#pragma unroll
            for (int q = 0; q < 4; ++q) acc[mf][nf][q] = 0.f;
    float zs[4] = {0.f, 0.f, 0.f, 0.f};

    // prologue: stage chunk 0 into buf 0
    {
#pragma unroll
        for (int m = 0; m < 4; ++m) {
            int idx = tid + 256 * m;
            int jl = idx >> 5, q = idx & 31;
            cpa16(&sWh[0][jl * WPITCH + q * 4],
                  gWh + ((size_t)c0 * 32 + jl) * 128 + q * 4);
        }
        if (tid < 64)
            cpa16(&((float4*)sJP[0])[tid],
                  (const float4*)(gJP + (size_t)c0 * JC * 4) + tid);
        cpcommit();
    }

    for (int c = 0; c < NCH; ++c) {
        cpwait0();
        __syncthreads();
        int cur = c & 1, nxt = cur ^ 1;

        if (c + 1 < NCH) {     // stage chunk c+1 into buf nxt
#pragma unroll
            for (int m = 0; m < 4; ++m) {
                int idx = tid + 256 * m;
                int jl = idx >> 5, q = idx & 31;
                cpa16(&sWh[nxt][jl * WPITCH + q * 4],
                      gWh + ((size_t)(c0 + c + 1) * 32 + jl) * 128 + q * 4);
            }
            if (tid < 64)
                cpa16(&((float4*)sJP[nxt])[tid],
                      (const float4*)(gJP + (size_t)(c0 + c + 1) * JC * 4) + tid);
        }
        cpcommit();

        uint mk[4];
        mk[0] = sMask[(rl0 +  0) * 16 + c];
        mk[1] = sMask[(rl0 +  8) * 16 + c];
        mk[2] = sMask[(rl0 + 16) * 16 + c];
        mk[3] = sMask[(rl0 + 24) * 16 + c];

        const float*  whc = sWh[cur];
        const float2* jpc = sJP[cur];

#pragma unroll
        for (int kf = 0; kf < 4; ++kf) {
            int jl0 = 8 * kf + cl, jl1 = jl0 + 4;
            float2 ua = jpc[jl0 * 4 + h];              // {u, v} at j = jl0
            float2 ub = jpc[jl1 * 4 + h];

            uint b0[4], b1[4];
#pragma unroll
            for (int nf = 0; nf < 4; ++nf) {           // pre-rounded: raw bits are tf32
                b0[nf] = __float_as_uint(whc[jl0 * WPITCH + h * 32 + nf * 8 + g]);
                b1[nf] = __float_as_uint(whc[jl1 * WPITCH + h * 32 + nf * 8 + g]);
            }

#pragma unroll
            for (int mf = 0; mf < 2; ++mf) {
                float2 eA = e[2 * mf], eB = e[2 * mf + 1];
                uint mA = mk[2 * mf], mB = mk[2 * mf + 1];
                float pv00 = fmaxf(eA.x * ua.x, eA.y * ua.y);   // (r0, jl0)
                float pv10 = fmaxf(eB.x * ua.x, eB.y * ua.y);   // (r1, jl0)
                float pv01 = fmaxf(eA.x * ub.x, eA.y * ub.y);   // (r0, jl1)
                float pv11 = fmaxf(eB.x * ub.x, eB.y * ub.y);   // (r1, jl1)
                uint a0 = cvt_tf32(pv00) & bit_mask1(mA, jl0);
                uint a1 = cvt_tf32(pv10) & bit_mask1(mB, jl0);
                uint a2 = cvt_tf32(pv01) & bit_mask1(mA, jl1);
                uint a3 = cvt_tf32(pv11) & bit_mask1(mB, jl1);
                zs[2 * mf]     += __uint_as_float(a0) + __uint_as_float(a2);  // row r0
                zs[2 * mf + 1] += __uint_as_float(a1) + __uint_as_float(a3);  // row r1
#pragma unroll
                for (int nf = 0; nf < 4; ++nf)
                    mma8(acc[mf][nf], a0, a1, a2, a3, b0[nf], b1[nf]);
            }
        }
    }

    // ---- z: per-row sums, reduce over the 4 cl-lanes sharing each row ----
    float z[4];
#pragma unroll
    for (int r = 0; r < 4; ++r) {
        z[r] = zs[r];
        z[r] += __shfl_xor_sync(0xffffffffu, z[r], 1);
        z[r] += __shfl_xor_sync(0xffffffffu, z[r], 2);
    }
    size_t sbase = (size_t)sp * BB * NN;
    if (cl == 0) {
        g_pz[(sbase + bn + ibase + rl0 +  0) * HE + h] = z[0];
        g_pz[(sbase + bn + ibase + rl0 +  8) * HE + h] = z[1];
        g_pz[(sbase + bn + ibase + rl0 + 16) * HE + h] = z[2];
        g_pz[(sbase + bn + ibase + rl0 + 24) * HE + h] = z[3];
    }

    // ---- store unnormalized partial accumulators ----
#pragma unroll
    for (int mf = 0; mf < 2; ++mf) {
        int row0 = ibase + mh * 32 + mf * 16 + g;
        int row1 = row0 + 8;
#pragma unroll
        for (int nf = 0; nf < 4; ++nf) {
            int dim = h * 32 + nf * 8 + 2 * cl;
            *(float2*)&g_pacc[(sbase + bn + row0) * 128 + dim] =
                make_float2(acc[mf][nf][0], acc[mf][nf][1]);
            *(float2*)&g_pacc[(sbase + bn + row1) * 128 + dim] =
                make_float2(acc[mf][nf][2], acc[mf][nf][3]);
        }
    }
}

// ---------------- K5: combine 4 partials + normalize ----------------
__global__ __launch_bounds__(256) void k_reduce(float* __restrict__ out) {
    int idx = blockIdx.x * 256 + threadIdx.x;
    int row = idx >> 5, q = idx & 31;
    int h = q >> 3;

    float z = 0.f;
#pragma unroll
    for (int s = 0; s < SPLIT; ++s)
        z += g_pz[((size_t)s * BB * NN + row) * HE + h];

    float4 acc = make_float4(0.f, 0.f, 0.f, 0.f);
#pragma unroll
    for (int s = 0; s < SPLIT; ++s) {
        float4 v = *(const float4*)&g_pacc[((size_t)s * BB * NN + row) * 128 + q * 4];
        acc.x += v.x; acc.y += v.y; acc.z += v.z; acc.w += v.w;
    }
    float rz = 1.0f / z;
    ((float4*)out)[idx] = make_float4(acc.x * rz, acc.y * rz, acc.z * rz, acc.w * rz);
}

// ---------------- launch ----------------
extern "C" void kernel_launch(void* const* d_in, const int* in_sizes, int n_in,
                              void* d_out, int out_size) {
    const float* h = nullptr;
    const int*   A = nullptr;
    const float* W = nullptr;
    const float* a = nullptr;
    for (int i = 0; i < n_in; ++i) {
        switch (in_sizes[i]) {
            case BB * NN * 128:      h = (const float*)d_in[i]; break;
            case 128 * 128:          W = (const float*)d_in[i]; break;
            case 2 * HD:             a = (const float*)d_in[i]; break;
            default:                 A = (const int*)d_in[i];   break;
        }
    }
    float* out = (float*)d_out;

    k_mm    <<<(BB * NN) / 64, 256>>>(h, W);
    k_params<<<(BB * NN * HE) / 256, 256>>>(a);
    k_pack  <<<4096, 256>>>(A);
    k_attn  <<<BB * (NN / 64) * SPLIT, 256>>>();
    k_reduce<<<(BB * NN * 32) / 256, 256>>>(out);
}

// round 17
// speedup vs baseline: 2.4726x; 1.1391x over previous
#include <cuda_runtime.h>
#include <cstdint>
#include <cstddef>

#define BB 8
#define NN 2048
#define HE 4
#define HD 32
#define SPLIT 4
#define NCH ((NN / SPLIT) / 32)      // 16 chunks of 32 j per CTA
#define WPITCH 136                   // smem row pitch: bank = 8*cl+g, conflict-free

typedef unsigned long long ull;
typedef unsigned int uint;

// ---------------- device scratch ----------------
__device__ float    g_Whr[BB * NN * 128];           // 8 MB  tf32-rounded Wh
__device__ float2   g_ip2[BB * NN * HE];            // {e^s, e^{0.2s}}
__device__ float2   g_jp2[BB * NN * HE];            // {e^t, e^{0.2t}}
__device__ unsigned g_Ab[BB * NN * (NN / 32)];      // packed adjacency
__device__ float    g_pacc[SPLIT * BB * NN * 128];  // unnormalized partials
__device__ float    g_pz[SPLIT * BB * NN * HE];     // partial row sums

// ---------------- helpers ----------------
__device__ __forceinline__ uint cvt_tf32(float f) {
    uint u; asm("cvt.rna.tf32.f32 %0, %1;" : "=r"(u) : "f"(f)); return u;
}
__device__ __forceinline__ uint bit_mask1(uint m, int b) {   // bit b -> 0 or 0xffffffff
    uint r; asm("bfe.s32 %0, %1, %2, 1;" : "=r"(r) : "r"(m), "r"(b)); return r;
}
// p_bits & maskSE & 0xffffe000 in one LOP3 (AND3 immLut = 0x80):
// truncates p to tf32 (RZ) and applies adjacency mask in a single ALU op.
__device__ __forceinline__ uint mask_trunc(float p, uint se) {
    uint r;
    asm("lop3.b32 %0, %1, %2, 0xffffe000, 0x80;"
        : "=r"(r) : "r"(__float_as_uint(p)), "r"(se));
    return r;
}
__device__ __forceinline__ void mma8(float* d, uint a0, uint a1, uint a2, uint a3,
                                     uint b0, uint b1) {
    asm("mma.sync.aligned.m16n8k8.row.col.f32.tf32.tf32.f32 "
        "{%0,%1,%2,%3},{%4,%5,%6,%7},{%8,%9},{%0,%1,%2,%3};"
        : "+f"(d[0]), "+f"(d[1]), "+f"(d[2]), "+f"(d[3])
        : "r"(a0), "r"(a1), "r"(a2), "r"(a3), "r"(b0), "r"(b1));
}
__device__ __forceinline__ void cpa16(void* dst, const void* src) {
    unsigned d = (unsigned)__cvta_generic_to_shared(dst);
    asm volatile("cp.async.cg.shared.global [%0], [%1], 16;" :: "r"(d), "l"(src));
}
__device__ __forceinline__ void cpcommit() { asm volatile("cp.async.commit_group;"); }
__device__ __forceinline__ void cpwait0()  { asm volatile("cp.async.wait_group 0;"); }

// ---------------- K1: Wh = h @ W  (emits tf32-rounded Wh only) ------------
__global__ __launch_bounds__(256) void k_mm(const float* __restrict__ hmat,
                                            const float* __restrict__ W) {
    __shared__ float hs[64 * 36];
    __shared__ float Ws[32 * 128];
    int tid = threadIdx.x;
    int tx = tid & 15, ty = tid >> 4;
    int rbase = blockIdx.x * 64;

    float acc[4][8];
#pragma unroll
    for (int i = 0; i < 4; ++i)
#pragma unroll
        for (int j = 0; j < 8; ++j) acc[i][j] = 0.f;

    for (int k0 = 0; k0 < 128; k0 += 32) {
        __syncthreads();
#pragma unroll
        for (int m = 0; m < 2; ++m) {
            int idx = tid * 2 + m;
            int r = idx >> 3, q = idx & 7;
            *(float4*)(hs + r * 36 + q * 4) =
                *(const float4*)(hmat + (size_t)(rbase + r) * 128 + k0 + q * 4);
        }
#pragma unroll
        for (int m = 0; m < 4; ++m) {
            int idx = tid + 256 * m;
            int kk = idx >> 5, c4 = idx & 31;
            *(float4*)(Ws + kk * 128 + c4 * 4) =
                *(const float4*)(W + (size_t)(k0 + kk) * 128 + c4 * 4);
        }
        __syncthreads();
#pragma unroll
        for (int kk = 0; kk < 32; ++kk) {
            float av[4], bv[8];
#pragma unroll
            for (int i = 0; i < 4; ++i) av[i] = hs[(ty * 4 + i) * 36 + kk];
#pragma unroll
            for (int j = 0; j < 8; ++j) bv[j] = Ws[kk * 128 + tx + 16 * j];
#pragma unroll
            for (int i = 0; i < 4; ++i)
#pragma unroll
                for (int j = 0; j < 8; ++j) acc[i][j] += av[i] * bv[j];
        }
    }
#pragma unroll
    for (int i = 0; i < 4; ++i)
#pragma unroll
        for (int j = 0; j < 8; ++j) {
            size_t idx = (size_t)(rbase + ty * 4 + i) * 128 + tx + 16 * j;
            g_Whr[idx] = __uint_as_float(cvt_tf32(acc[i][j]));
        }
}

// ---------------- K2: per-(node,head) params (from rounded Wh) ------------
__global__ __launch_bounds__(256) void k_params(const float* __restrict__ a) {
    __shared__ float sa[64];
    int tid = threadIdx.x;
    if (tid < 64) sa[tid] = a[tid];
    __syncthreads();
    int idx = blockIdx.x * 256 + tid;
    int nh = idx >> 2, hh = idx & 3;
    const float4* wh = (const float4*)(g_Whr + (size_t)nh * 128 + hh * 32);
    float s = 0.f, t = 0.f;
#pragma unroll
    for (int k = 0; k < 8; ++k) {
        float4 w = wh[k];
        s += w.x * sa[4 * k + 0] + w.y * sa[4 * k + 1] + w.z * sa[4 * k + 2] + w.w * sa[4 * k + 3];
        t += w.x * sa[32 + 4 * k + 0] + w.y * sa[32 + 4 * k + 1] + w.z * sa[32 + 4 * k + 2] + w.w * sa[32 + 4 * k + 3];
    }
    g_ip2[idx] = make_float2(expf(s), expf(0.2f * s));
    g_jp2[idx] = make_float2(expf(t), expf(0.2f * t));
}

// ---------------- K3: pack A into bitmasks ----------------
__global__ __launch_bounds__(256) void k_pack(const int* __restrict__ A) {
    int gt = blockIdx.x * 256 + threadIdx.x;
    int warpId = gt >> 5, lane = gt & 31;
    const int* src = A + (size_t)warpId * 1024;
    unsigned keep = 0;
#pragma unroll
    for (int g = 0; g < 32; ++g) {
        int v = src[g * 32 + lane];
        unsigned m = __ballot_sync(0xffffffffu, v > 0);
        if (g == lane) keep = m;
    }
    g_Ab[(size_t)warpId * 32 + lane] = keep;
}

// ---------------- K4: fused attention via mma.sync tf32 ---------------------
// CTA = (split, batch, 64-row i-tile); 256 threads = 8 warps = (4 heads x 2
// m-halves). Warp computes out[32 rows, 32 dims] for head h over 512 j's.
// A-fragments: p = max(E1*u, E2*v), masked + RZ-truncated to tf32 by ONE LOP3;
// z sums the exact truncated bits fed to the mma (self-consistent softmax).
// B operand: pre-rounded g_Whr, raw-bit loads, pitch 136 -> conflict-free.
__global__ __launch_bounds__(256, 2) void k_attn() {
    constexpr int JC = 32;
    __shared__ float    sWh[2][JC * WPITCH];   // 34816 B
    __shared__ float2   sJP[2][JC * HE];       // 2048 B
    __shared__ unsigned sMask[64 * 16];        // [row_local][chunk] 4096 B

    int tid = threadIdx.x;
    int warp = tid >> 5, lane = tid & 31;
    int h = warp & 3, mh = warp >> 2;
    int g = lane >> 2, cl = lane & 3;

    int sp = blockIdx.x & 3;
    int blk = blockIdx.x >> 2;
    int b = blk >> 5;
    int ibase = (blk & 31) << 6;               // 64-row i-tile
    size_t bn = (size_t)b * NN;
    int c0 = sp * NCH;                         // first chunk (== mask word idx)

    const float*  gWh = g_Whr + bn * 128;
    const float2* gJP = g_jp2 + bn * 4;

    int rl0 = mh * 32 + g;
    float2 e[4];
    e[0] = g_ip2[(bn + ibase + rl0 +  0) * 4 + h];
    e[1] = g_ip2[(bn + ibase + rl0 +  8) * 4 + h];
    e[2] = g_ip2[(bn + ibase + rl0 + 16) * 4 + h];
    e[3] = g_ip2[(bn + ibase + rl0 + 24) * 4 + h];

    // preload adjacency words: sMask[r][ch], r<64, ch<16
#pragma unroll
    for (int m = 0; m < 4; ++m) {
        int idx = tid + 256 * m;
        int r = idx >> 4, ch = idx & 15;
        sMask[r * 16 + ch] = g_Ab[(bn + ibase + r) * 64 + c0 + ch];
    }

    float acc[2][4][4];
#pragma unroll
    for (int mf = 0; mf < 2; ++mf)
#pragma unroll
        for (int nf = 0; nf < 4; ++nf)
#pragma unroll
            for (int q = 0; q < 4; ++q) acc[mf][nf][q] = 0.f;
    float zs[4] = {0.f, 0.f, 0.f, 0.f};

    // prologue: stage chunk 0 into buf 0
    {
#pragma unroll
        for (int m = 0; m < 4; ++m) {
            int idx = tid + 256 * m;
            int jl = idx >> 5, q = idx & 31;
            cpa16(&sWh[0][jl * WPITCH + q * 4],
                  gWh + ((size_t)c0 * 32 + jl) * 128 + q * 4);
        }
        if (tid < 64)
            cpa16(&((float4*)sJP[0])[tid],
                  (const float4*)(gJP + (size_t)c0 * JC * 4) + tid);
        cpcommit();
    }

    for (int c = 0; c < NCH; ++c) {
        cpwait0();
        __syncthreads();
        int cur = c & 1, nxt = cur ^ 1;

        if (c + 1 < NCH) {     // stage chunk c+1 into buf nxt
#pragma unroll
            for (int m = 0; m < 4; ++m) {
                int idx = tid + 256 * m;
                int jl = idx >> 5, q = idx & 31;
                cpa16(&sWh[nxt][jl * WPITCH + q * 4],
                      gWh + ((size_t)(c0 + c + 1) * 32 + jl) * 128 + q * 4);
            }
            if (tid < 64)
                cpa16(&((float4*)sJP[nxt])[tid],
                      (const float4*)(gJP + (size_t)(c0 + c + 1) * JC * 4) + tid);
        }
        cpcommit();

        uint mk[4];
        mk[0] = sMask[(rl0 +  0) * 16 + c];
        mk[1] = sMask[(rl0 +  8) * 16 + c];
        mk[2] = sMask[(rl0 + 16) * 16 + c];
        mk[3] = sMask[(rl0 + 24) * 16 + c];

        const float*  whc = sWh[cur];
        const float2* jpc = sJP[cur];

#pragma unroll
        for (int kf = 0; kf < 4; ++kf) {
            int jl0 = 8 * kf + cl, jl1 = jl0 + 4;
            float2 ua = jpc[jl0 * 4 + h];              // {u, v} at j = jl0
            float2 ub = jpc[jl1 * 4 + h];

            uint b0[4], b1[4];
#pragma unroll
            for (int nf = 0; nf < 4; ++nf) {           // pre-rounded: raw bits are tf32
                b0[nf] = __float_as_uint(whc[jl0 * WPITCH + h * 32 + nf * 8 + g]);
                b1[nf] = __float_as_uint(whc[jl1 * WPITCH + h * 32 + nf * 8 + g]);
            }

#pragma unroll
            for (int mf = 0; mf < 2; ++mf) {
                float2 eA = e[2 * mf], eB = e[2 * mf + 1];
                uint mA = mk[2 * mf], mB = mk[2 * mf + 1];
                float pv00 = fmaxf(eA.x * ua.x, eA.y * ua.y);   // (r0, jl0)
                float pv10 = fmaxf(eB.x * ua.x, eB.y * ua.y);   // (r1, jl0)
                float pv01 = fmaxf(eA.x * ub.x, eA.y * ub.y);   // (r0, jl1)
                float pv11 = fmaxf(eB.x * ub.x, eB.y * ub.y);   // (r1, jl1)
                uint a0 = mask_trunc(pv00, bit_mask1(mA, jl0));
                uint a1 = mask_trunc(pv10, bit_mask1(mB, jl0));
                uint a2 = mask_trunc(pv01, bit_mask1(mA, jl1));
                uint a3 = mask_trunc(pv11, bit_mask1(mB, jl1));
                zs[2 * mf]     += __uint_as_float(a0) + __uint_as_float(a2);  // row r0
                zs[2 * mf + 1] += __uint_as_float(a1) + __uint_as_float(a3);  // row r1
#pragma unroll
                for (int nf = 0; nf < 4; ++nf)
                    mma8(acc[mf][nf], a0, a1, a2, a3, b0[nf], b1[nf]);
            }
        }
    }

    // ---- z: per-row sums, reduce over the 4 cl-lanes sharing each row ----
    float z[4];
#pragma unroll
    for (int r = 0; r < 4; ++r) {
        z[r] = zs[r];
        z[r] += __shfl_xor_sync(0xffffffffu, z[r], 1);
        z[r] += __shfl_xor_sync(0xffffffffu, z[r], 2);
    }
    size_t sbase = (size_t)sp * BB * NN;
    if (cl == 0) {
        g_pz[(sbase + bn + ibase + rl0 +  0) * HE + h] = z[0];
        g_pz[(sbase + bn + ibase + rl0 +  8) * HE + h] = z[1];
        g_pz[(sbase + bn + ibase + rl0 + 16) * HE + h] = z[2];
        g_pz[(sbase + bn + ibase + rl0 + 24) * HE + h] = z[3];
    }

    // ---- store unnormalized partial accumulators ----
#pragma unroll
    for (int mf = 0; mf < 2; ++mf) {
        int row0 = ibase + mh * 32 + mf * 16 + g;
        int row1 = row0 + 8;
#pragma unroll
        for (int nf = 0; nf < 4; ++nf) {
            int dim = h * 32 + nf * 8 + 2 * cl;
            *(float2*)&g_pacc[(sbase + bn + row0) * 128 + dim] =
                make_float2(acc[mf][nf][0], acc[mf][nf][1]);
            *(float2*)&g_pacc[(sbase + bn + row1) * 128 + dim] =
                make_float2(acc[mf][nf][2], acc[mf][nf][3]);
        }
    }
}

// ---------------- K5: combine 4 partials + normalize ----------------
__global__ __launch_bounds__(256) void k_reduce(float* __restrict__ out) {
    int idx = blockIdx.x * 256 + threadIdx.x;
    int row = idx >> 5, q = idx & 31;
    int h = q >> 3;

    float z = 0.f;
#pragma unroll
    for (int s = 0; s < SPLIT; ++s)
        z += g_pz[((size_t)s * BB * NN + row) * HE + h];

    float4 acc = make_float4(0.f, 0.f, 0.f, 0.f);
#pragma unroll
    for (int s = 0; s < SPLIT; ++s) {
        float4 v = *(const float4*)&g_pacc[((size_t)s * BB * NN + row) * 128 + q * 4];
        acc.x += v.x; acc.y += v.y; acc.z += v.z; acc.w += v.w;
    }
    float rz = 1.0f / z;
    ((float4*)out)[idx] = make_float4(acc.x * rz, acc.y * rz, acc.z * rz, acc.w * rz);
}

// ---------------- launch ----------------
extern "C" void kernel_launch(void* const* d_in, const int* in_sizes, int n_in,
                              void* d_out, int out_size) {
    const float* h = nullptr;
    const int*   A = nullptr;
    const float* W = nullptr;
    const float* a = nullptr;
    for (int i = 0; i < n_in; ++i) {
        switch (in_sizes[i]) {
            case BB * NN * 128:      h = (const float*)d_in[i]; break;
            case 128 * 128:          W = (const float*)d_in[i]; break;
            case 2 * HD:             a = (const float*)d_in[i]; break;
            default:                 A = (const int*)d_in[i];   break;
        }
    }
    float* out = (float*)d_out;

    k_mm    <<<(BB * NN) / 64, 256>>>(h, W);
    k_params<<<(BB * NN * HE) / 256, 256>>>(a);
    k_pack  <<<4096, 256>>>(A);
    k_attn  <<<BB * (NN / 64) * SPLIT, 256>>>();
    k_reduce<<<(BB * NN * 32) / 256, 256>>>(out);
}